// round 1
// baseline (speedup 1.0000x reference)
#include <cuda_runtime.h>
#include <math.h>

// Shapes (fixed for this problem)
#define BS_TOT 4096   // B*S
#define S_LEN  2048
#define D_EMB  1536
#define D_AUG  512

// Scratch: only heads 0..3 of qh/kh/vh/attn are ever nonzero-relevant.
__device__ float g_qh[BS_TOT * D_AUG];
__device__ float g_kh[BS_TOT * D_AUG];
__device__ float g_vh[BS_TOT * D_AUG];
__device__ float g_attn[BS_TOT * D_AUG];

// ---------------------------------------------------------------------------
// Generic fp32 SGEMM: C[M,N] = A[M,K] @ B[N,K]^T   (row-major, strided)
// Tile 128x128, BK=8, 256 threads, 8x8 micro-tile per thread.
// Requires: M%128==0, N%128==0, K%8==0, 16B-aligned rows. All true here.
// ---------------------------------------------------------------------------
__global__ __launch_bounds__(256, 2)
void gemm_tn(const float* __restrict__ A, int lda,
             const float* __restrict__ B, int ldb,
             float* __restrict__ C, int ldc, int K)
{
    __shared__ float As[8][128];
    __shared__ float Bs[8][128];
    const int tid = threadIdx.x;
    const int tx  = tid & 15, ty = tid >> 4;
    const int m0  = blockIdx.y * 128, n0 = blockIdx.x * 128;
    const int lrow = tid >> 1, lk4 = (tid & 1) * 4;
    const float* Ap = A + (size_t)(m0 + lrow) * lda + lk4;
    const float* Bp = B + (size_t)(n0 + lrow) * ldb + lk4;

    float acc[8][8];
#pragma unroll
    for (int i = 0; i < 8; i++)
#pragma unroll
        for (int j = 0; j < 8; j++) acc[i][j] = 0.f;

    for (int k0 = 0; k0 < K; k0 += 8) {
        float4 av = *(const float4*)(Ap + k0);
        float4 bv = *(const float4*)(Bp + k0);
        __syncthreads();
        As[lk4 + 0][lrow] = av.x; As[lk4 + 1][lrow] = av.y;
        As[lk4 + 2][lrow] = av.z; As[lk4 + 3][lrow] = av.w;
        Bs[lk4 + 0][lrow] = bv.x; Bs[lk4 + 1][lrow] = bv.y;
        Bs[lk4 + 2][lrow] = bv.z; Bs[lk4 + 3][lrow] = bv.w;
        __syncthreads();
#pragma unroll
        for (int kk = 0; kk < 8; kk++) {
            float4 a0 = *(const float4*)&As[kk][ty * 8];
            float4 a1 = *(const float4*)&As[kk][ty * 8 + 4];
            float4 b0 = *(const float4*)&Bs[kk][tx * 4];         // cols n0+tx*4..+3
            float4 b1 = *(const float4*)&Bs[kk][64 + tx * 4];    // cols n0+64+tx*4..+3
            float aa[8] = {a0.x, a0.y, a0.z, a0.w, a1.x, a1.y, a1.z, a1.w};
            float bb[8] = {b0.x, b0.y, b0.z, b0.w, b1.x, b1.y, b1.z, b1.w};
#pragma unroll
            for (int i = 0; i < 8; i++)
#pragma unroll
                for (int j = 0; j < 8; j++)
                    acc[i][j] = fmaf(aa[i], bb[j], acc[i][j]);
        }
    }

#pragma unroll
    for (int i = 0; i < 8; i++) {
        float* crow = C + (size_t)(m0 + ty * 8 + i) * ldc + n0;
        *(float4*)(crow + tx * 4)      = make_float4(acc[i][0], acc[i][1], acc[i][2], acc[i][3]);
        *(float4*)(crow + 64 + tx * 4) = make_float4(acc[i][4], acc[i][5], acc[i][6], acc[i][7]);
    }
}

// ---------------------------------------------------------------------------
// RoPE (interleaved-pair, torchtune convention), applied in-place to the
// 4 live heads of qh and kh. One thread per (row, head, pair).
// ---------------------------------------------------------------------------
__global__ void rope_kernel(float* __restrict__ qh, float* __restrict__ kh)
{
    int idx  = blockIdx.x * blockDim.x + threadIdx.x;  // 4096*4*64 = 1,048,576
    int pair = idx & 63;
    int h    = (idx >> 6) & 3;
    int m    = idx >> 8;
    int s    = m & (S_LEN - 1);

    // freq = 10000^{-2*pair/128}; computed in double -> round to f32 (matches
    // jnp's f32 value to ~1 ulp).
    float freq = (float)exp(-(double)(2 * pair) * (1.0 / 128.0) * 9.210340371976184);
    float ang  = (float)s * freq;
    float c, sn;
    sincosf(ang, &sn, &c);

    size_t off = (size_t)m * D_AUG + h * 128 + 2 * pair;
    float q1 = qh[off], q2 = qh[off + 1];
    qh[off]     = q1 * c - q2 * sn;
    qh[off + 1] = q1 * sn + q2 * c;
    float k1 = kh[off], k2 = kh[off + 1];
    kh[off]     = k1 * c - k2 * sn;
    kh[off + 1] = k1 * sn + k2 * c;
}

// ---------------------------------------------------------------------------
// Flash attention, fp32, causal, per (batch, head) with head in 0..3.
// Q block 64 rows per CTA; loop over key blocks 0..qb.
// grid = (32 query blocks, 8 batch*head), 256 threads.
// Dynamic smem: Qs[128][64] + KVs(8192 f) + Ps[64][64] = 80 KiB.
// ---------------------------------------------------------------------------
__global__ __launch_bounds__(256)
void flash_kernel(const float* __restrict__ QH, const float* __restrict__ KH,
                  const float* __restrict__ VH, float* __restrict__ OUT)
{
    extern __shared__ float sm[];
    float* Qs  = sm;          // transposed: [kk][r], 128*64
    float* KVs = sm + 8192;   // K phase: [kk][c] 128*64 ; V phase: [c][d] 64*128
    float* Ps  = sm + 16384;  // transposed P: [c][r], 64*64

    const int qb = blockIdx.x;
    const int bh = blockIdx.y;
    const size_t base = (size_t)(bh >> 2) * S_LEN * D_AUG + (size_t)(bh & 3) * 128;
    const float* Qg = QH + base;
    const float* Kg = KH + base;
    const float* Vg = VH + base;
    float*       Og = OUT + base;

    const int tid = threadIdx.x;
    const int tx = tid & 15, ty = tid >> 4;
    const float qscale = 0.08838834764831845f;  // 1/sqrt(128)

    // Load Q tile (scaled), transposed into Qs[kk][r]
    for (int idx = tid; idx < 64 * 32; idx += 256) {
        int r = idx >> 5, c4 = (idx & 31) * 4;
        float4 v = *(const float4*)(Qg + (size_t)(qb * 64 + r) * D_AUG + c4);
        Qs[(c4 + 0) * 64 + r] = v.x * qscale;
        Qs[(c4 + 1) * 64 + r] = v.y * qscale;
        Qs[(c4 + 2) * 64 + r] = v.z * qscale;
        Qs[(c4 + 3) * 64 + r] = v.w * qscale;
    }

    float m_i[4], l_i[4], o[4][8];
#pragma unroll
    for (int i = 0; i < 4; i++) { m_i[i] = -INFINITY; l_i[i] = 0.f; }
#pragma unroll
    for (int i = 0; i < 4; i++)
#pragma unroll
        for (int j = 0; j < 8; j++) o[i][j] = 0.f;

    for (int jb = 0; jb <= qb; jb++) {
        __syncthreads();  // prior iter's PV reads of KVs/Ps are done
        // Load K tile jb, transposed into KVs[kk][c]
        for (int idx = tid; idx < 64 * 32; idx += 256) {
            int r = idx >> 5, c4 = (idx & 31) * 4;
            float4 v = *(const float4*)(Kg + (size_t)(jb * 64 + r) * D_AUG + c4);
            KVs[(c4 + 0) * 64 + r] = v.x;
            KVs[(c4 + 1) * 64 + r] = v.y;
            KVs[(c4 + 2) * 64 + r] = v.z;
            KVs[(c4 + 3) * 64 + r] = v.w;
        }
        __syncthreads();

        // Scores: S[r][c] for r = ty*4+ii, c = tx*4+jj
        float sc[4][4];
#pragma unroll
        for (int i = 0; i < 4; i++)
#pragma unroll
            for (int j = 0; j < 4; j++) sc[i][j] = 0.f;
#pragma unroll 4
        for (int kk = 0; kk < 128; kk++) {
            float4 a = *(const float4*)&Qs[kk * 64 + ty * 4];
            float4 b = *(const float4*)&KVs[kk * 64 + tx * 4];
            float aa[4] = {a.x, a.y, a.z, a.w};
            float bb[4] = {b.x, b.y, b.z, b.w};
#pragma unroll
            for (int i = 0; i < 4; i++)
#pragma unroll
                for (int j = 0; j < 4; j++)
                    sc[i][j] = fmaf(aa[i], bb[j], sc[i][j]);
        }

        if (jb == qb) {  // causal mask within diagonal tile
#pragma unroll
            for (int i = 0; i < 4; i++)
#pragma unroll
                for (int j = 0; j < 4; j++)
                    if (tx * 4 + j > ty * 4 + i) sc[i][j] = -1e30f;
        }

        // Online softmax update (row stats shared across the 16 tx lanes)
        float scl[4];
#pragma unroll
        for (int i = 0; i < 4; i++) {
            float mt = fmaxf(fmaxf(sc[i][0], sc[i][1]), fmaxf(sc[i][2], sc[i][3]));
#pragma unroll
            for (int off = 1; off < 16; off <<= 1)
                mt = fmaxf(mt, __shfl_xor_sync(0xffffffffu, mt, off));
            float mnew = fmaxf(m_i[i], mt);
            scl[i] = expf(m_i[i] - mnew);
            float s0 = 0.f;
#pragma unroll
            for (int j = 0; j < 4; j++) {
                float p = expf(sc[i][j] - mnew);
                sc[i][j] = p;
                s0 += p;
            }
#pragma unroll
            for (int off = 1; off < 16; off <<= 1)
                s0 += __shfl_xor_sync(0xffffffffu, s0, off);
            l_i[i] = l_i[i] * scl[i] + s0;
            m_i[i] = mnew;
        }
#pragma unroll
        for (int i = 0; i < 4; i++)
#pragma unroll
            for (int j = 0; j < 8; j++) o[i][j] *= scl[i];

        __syncthreads();  // everyone done reading KVs (K) and prior Ps
        // Store P transposed; load V tile into KVs as [c][d]
#pragma unroll
        for (int i = 0; i < 4; i++)
#pragma unroll
            for (int j = 0; j < 4; j++)
                Ps[(tx * 4 + j) * 64 + ty * 4 + i] = sc[i][j];
        for (int idx = tid; idx < 64 * 32; idx += 256) {
            int c = idx >> 5, d4 = (idx & 31) * 4;
            *(float4*)&KVs[c * 128 + d4] =
                *(const float4*)(Vg + (size_t)(jb * 64 + c) * D_AUG + d4);
        }
        __syncthreads();

        // O += P @ V : O cols tx*4..+3 and 64+tx*4..+3 (conflict-free LDS.128)
#pragma unroll 2
        for (int c = 0; c < 64; c++) {
            float4 p  = *(const float4*)&Ps[c * 64 + ty * 4];
            float4 v0 = *(const float4*)&KVs[c * 128 + tx * 4];
            float4 v1 = *(const float4*)&KVs[c * 128 + 64 + tx * 4];
            float pp[4] = {p.x, p.y, p.z, p.w};
            float va[4] = {v0.x, v0.y, v0.z, v0.w};
            float vb[4] = {v1.x, v1.y, v1.z, v1.w};
#pragma unroll
            for (int i = 0; i < 4; i++) {
#pragma unroll
                for (int j = 0; j < 4; j++) {
                    o[i][j]     = fmaf(pp[i], va[j], o[i][j]);
                    o[i][j + 4] = fmaf(pp[i], vb[j], o[i][j + 4]);
                }
            }
        }
    }

    // Epilogue: divide by l, write out
#pragma unroll
    for (int i = 0; i < 4; i++) {
        float inv = 1.0f / l_i[i];
        float* orow = Og + (size_t)(qb * 64 + ty * 4 + i) * D_AUG;
        *(float4*)(orow + tx * 4) =
            make_float4(o[i][0] * inv, o[i][1] * inv, o[i][2] * inv, o[i][3] * inv);
        *(float4*)(orow + 64 + tx * 4) =
            make_float4(o[i][4] * inv, o[i][5] * inv, o[i][6] * inv, o[i][7] * inv);
    }
}

// ---------------------------------------------------------------------------
extern "C" void kernel_launch(void* const* d_in, const int* in_sizes, int n_in,
                              void* d_out, int out_size)
{
    const float* q  = (const float*)d_in[0];
    const float* k  = (const float*)d_in[1];
    const float* v  = (const float*)d_in[2];
    const float* Wq = (const float*)d_in[3];
    const float* Wk = (const float*)d_in[4];
    const float* Wv = (const float*)d_in[5];
    const float* Wo = (const float*)d_in[6];
    float* out = (float*)d_out;

    float *qh, *kh, *vh, *attn;
    cudaGetSymbolAddress((void**)&qh,   g_qh);
    cudaGetSymbolAddress((void**)&kh,   g_kh);
    cudaGetSymbolAddress((void**)&vh,   g_vh);
    cudaGetSymbolAddress((void**)&attn, g_attn);

    dim3 blk(256);

    // qh[:, :512] = q @ W_q[:512]^T   (heads 4..11 provably never needed)
    gemm_tn<<<dim3(4, 32), blk>>>(q, D_EMB, Wq, D_EMB, qh, D_AUG, D_EMB);
    // kh[:, :512] = k @ W_k[:512]^T
    gemm_tn<<<dim3(4, 32), blk>>>(k, D_EMB, Wk, D_EMB, kh, D_AUG, D_EMB);
    // vh = v[:, 512:1024] @ W_v^T
    gemm_tn<<<dim3(4, 32), blk>>>(v + D_AUG, D_EMB, Wv, D_AUG, vh, D_AUG, D_AUG);

    // RoPE in place on qh, kh (4 live heads)
    rope_kernel<<<4096, 256>>>(qh, kh);

    // Flash attention over heads 0..3, causal
    cudaFuncSetAttribute(flash_kernel, cudaFuncAttributeMaxDynamicSharedMemorySize, 81920);
    flash_kernel<<<dim3(32, 8), blk, 81920>>>(qh, kh, vh, attn);

    // out = attn[:, :512] @ W_o[:, :512]^T  (attn cols 512.. are exactly 0)
    gemm_tn<<<dim3(12, 32), blk>>>(attn, D_AUG, Wo, D_EMB, out, D_EMB, D_AUG);
}

// round 3
// speedup vs baseline: 1.2868x; 1.2868x over previous
#include <cuda_runtime.h>
#include <cuda_bf16.h>
#include <math.h>
#include <stdint.h>

// Shapes (fixed for this problem)
#define BS_TOT 4096   // B*S
#define S_LEN  2048
#define D_EMB  1536
#define D_AUG  512

// ---------------- device scratch (allowed; no dynamic alloc) ----------------
__device__ float g_qh[BS_TOT * D_AUG];
__device__ float g_kh[BS_TOT * D_AUG];
__device__ float g_vh[BS_TOT * D_AUG];
__device__ float g_attn[BS_TOT * D_AUG];

// split-bf16 operands: A-side layout [hi | hi | lo], B-side [hi | lo | hi]
__device__ __align__(128) __nv_bfloat16 g_q_s   [BS_TOT * 3 * D_EMB];
__device__ __align__(128) __nv_bfloat16 g_k_s   [BS_TOT * 3 * D_EMB];
__device__ __align__(128) __nv_bfloat16 g_v_s   [BS_TOT * 3 * D_AUG];
__device__ __align__(128) __nv_bfloat16 g_attn_s[BS_TOT * 3 * D_AUG];
__device__ __align__(128) __nv_bfloat16 g_Wq_s  [D_AUG * 3 * D_EMB];
__device__ __align__(128) __nv_bfloat16 g_Wk_s  [D_AUG * 3 * D_EMB];
__device__ __align__(128) __nv_bfloat16 g_Wv_s  [D_AUG * 3 * D_AUG];
__device__ __align__(128) __nv_bfloat16 g_Wo_s  [D_EMB * 3 * D_AUG];

// ---------------------------------------------------------------------------
// Base-ISA async-copy / ldmatrix / mma helpers (sm_80+, safe on sm_103 base)
// ---------------------------------------------------------------------------
__device__ __forceinline__ uint32_t smem_u32(const void* p) {
    uint32_t a;
    asm("{ .reg .u64 t; cvta.to.shared.u64 t, %1; cvt.u32.u64 %0, t; }" : "=r"(a) : "l"(p));
    return a;
}
__device__ __forceinline__ void cp16(uint32_t saddr, const void* gaddr) {
    asm volatile("cp.async.cg.shared.global [%0], [%1], 16;" :: "r"(saddr), "l"(gaddr) : "memory");
}
__device__ __forceinline__ void cp_commit() {
    asm volatile("cp.async.commit_group;" ::: "memory");
}
template <int N>
__device__ __forceinline__ void cp_wait() {
    asm volatile("cp.async.wait_group %0;" :: "n"(N) : "memory");
}
__device__ __forceinline__ void ldmx4(uint32_t* r, uint32_t addr) {
    asm volatile("ldmatrix.sync.aligned.m8n8.x4.shared.b16 {%0,%1,%2,%3}, [%4];"
                 : "=r"(r[0]), "=r"(r[1]), "=r"(r[2]), "=r"(r[3]) : "r"(addr));
}
__device__ __forceinline__ void mma_bf16(float* c, const uint32_t* a, uint32_t b0, uint32_t b1) {
    asm volatile(
        "mma.sync.aligned.m16n8k16.row.col.f32.bf16.bf16.f32 "
        "{%0,%1,%2,%3}, {%4,%5,%6,%7}, {%8,%9}, {%0,%1,%2,%3};"
        : "+f"(c[0]), "+f"(c[1]), "+f"(c[2]), "+f"(c[3])
        : "r"(a[0]), "r"(a[1]), "r"(a[2]), "r"(a[3]), "r"(b0), "r"(b1));
}

// ---------------------------------------------------------------------------
// Split-precision conversion: dst rows of length 3K.
// bmode=0 (A-side): [hi | hi | lo]     bmode=1 (B-side): [hi | lo | hi]
// ---------------------------------------------------------------------------
__global__ void split3_kernel(const float* __restrict__ src, int sld,
                              __nv_bfloat16* __restrict__ dst, int K, int rows, int bmode)
{
    int K4 = K >> 2;
    int i = blockIdx.x * blockDim.x + threadIdx.x;
    if (i >= rows * K4) return;
    int r = i / K4, c4 = (i - r * K4) << 2;
    float4 x = *(const float4*)(src + (size_t)r * sld + c4);
    float xs[4] = {x.x, x.y, x.z, x.w};
    __nv_bfloat162 h0, h1, l0, l1;
    __nv_bfloat16 h[4], l[4];
#pragma unroll
    for (int j = 0; j < 4; j++) {
        h[j] = __float2bfloat16(xs[j]);
        l[j] = __float2bfloat16(xs[j] - __bfloat162float(h[j]));
    }
    h0.x = h[0]; h0.y = h[1]; h1.x = h[2]; h1.y = h[3];
    l0.x = l[0]; l0.y = l[1]; l1.x = l[2]; l1.y = l[3];
    __nv_bfloat16* d = dst + (size_t)r * 3 * K + c4;
    *(__nv_bfloat162*)(d)     = h0;  *(__nv_bfloat162*)(d + 2)     = h1;
    if (bmode == 0) {
        *(__nv_bfloat162*)(d + K)     = h0;  *(__nv_bfloat162*)(d + K + 2)     = h1;
        *(__nv_bfloat162*)(d + 2 * K) = l0;  *(__nv_bfloat162*)(d + 2 * K + 2) = l1;
    } else {
        *(__nv_bfloat162*)(d + K)     = l0;  *(__nv_bfloat162*)(d + K + 2)     = l1;
        *(__nv_bfloat162*)(d + 2 * K) = h0;  *(__nv_bfloat162*)(d + 2 * K + 2) = h1;
    }
}

// ---------------------------------------------------------------------------
// HMMA bf16 GEMM: C[M,N] = A[M,K3] @ B[N,K3]^T, fp32 accumulate.
// 128x128 CTA tile, BK=32, 3-stage cp.async pipeline, 8 warps (2Mx4N),
// warp tile 64x32 via mma.sync.m16n8k16. Padded smem stride 40 bf16
// (80B: 16B-aligned rows, conflict-free ldmatrix).
// ---------------------------------------------------------------------------
#define BM 128
#define BN 128
#define BK 32
#define LDSM 40                  // bf16 elements per smem row (padded)
#define STAGES 3
#define TSTG (BM * LDSM)         // bf16 elems per (A or B) stage = 5120
#define GEMM_SMEM (2 * STAGES * TSTG * 2)   // bytes = 61440

__global__ void __launch_bounds__(256, 1)
gemm_hmma(const __nv_bfloat16* __restrict__ A, const __nv_bfloat16* __restrict__ B,
          float* __restrict__ C, int K3, int ldc)
{
    extern __shared__ __align__(128) __nv_bfloat16 smem[];
    __nv_bfloat16* As = smem;                   // STAGES stages
    __nv_bfloat16* Bs = smem + STAGES * TSTG;

    const int tid  = threadIdx.x;
    const int wid  = tid >> 5, lane = tid & 31;
    const int m0   = blockIdx.y * BM, n0 = blockIdx.x * BN;
    const int wm   = (wid >> 2) * 64;           // warp M offset (0 or 64)
    const int wn   = (wid & 3) * 32;            // warp N offset

    // loader mapping: 512 16B-chunks per operand per stage; 2 per thread each
    const int lrow0 = tid >> 2;                 // chunk c = tid:    row, col16
    const int lq0   = tid & 3;
    const int lrow1 = (tid + 256) >> 2;         // chunk c = tid+256
    const int lq1   = (tid + 256) & 3;

    const __nv_bfloat16* Ag0 = A + (size_t)(m0 + lrow0) * K3 + lq0 * 8;
    const __nv_bfloat16* Ag1 = A + (size_t)(m0 + lrow1) * K3 + lq1 * 8;
    const __nv_bfloat16* Bg0 = B + (size_t)(n0 + lrow0) * K3 + lq0 * 8;
    const __nv_bfloat16* Bg1 = B + (size_t)(n0 + lrow1) * K3 + lq1 * 8;
    const uint32_t sA0 = smem_u32(As) + (lrow0 * LDSM + lq0 * 8) * 2;
    const uint32_t sA1 = smem_u32(As) + (lrow1 * LDSM + lq1 * 8) * 2;
    const uint32_t sB0 = smem_u32(Bs) + (lrow0 * LDSM + lq0 * 8) * 2;
    const uint32_t sB1 = smem_u32(Bs) + (lrow1 * LDSM + lq1 * 8) * 2;

    const int KT = K3 / BK;

    float acc[4][4][4];
#pragma unroll
    for (int i = 0; i < 4; i++)
#pragma unroll
        for (int j = 0; j < 4; j++)
#pragma unroll
            for (int t = 0; t < 4; t++) acc[i][j][t] = 0.f;

    // ldmatrix base addresses (per-thread row within tiles)
    const uint32_t als = smem_u32(As) + ((wm + (lane & 15)) * LDSM + (lane >> 4) * 8) * 2;
    const uint32_t bls = smem_u32(Bs) + ((wn + (lane & 15)) * LDSM + (lane >> 4) * 8) * 2;

    // prologue: preload STAGES-1 k-chunks
#pragma unroll
    for (int s = 0; s < STAGES - 1; s++) {
        int k0 = s * BK;
        cp16(sA0 + s * TSTG * 2, Ag0 + k0);
        cp16(sA1 + s * TSTG * 2, Ag1 + k0);
        cp16(sB0 + s * TSTG * 2, Bg0 + k0);
        cp16(sB1 + s * TSTG * 2, Bg1 + k0);
        cp_commit();
    }

    for (int it = 0; it < KT; it++) {
        cp_wait<STAGES - 2>();
        __syncthreads();
        const int sc = it % STAGES;
        const uint32_t abase = als + sc * TSTG * 2;
        const uint32_t bbase = bls + sc * TSTG * 2;
#pragma unroll
        for (int ks = 0; ks < 2; ks++) {
            uint32_t af[4][4], bf[2][4];
#pragma unroll
            for (int mt = 0; mt < 4; mt++)
                ldmx4(af[mt], abase + (mt * 16 * LDSM + ks * 16) * 2);
#pragma unroll
            for (int nt2 = 0; nt2 < 2; nt2++)
                ldmx4(bf[nt2], bbase + (nt2 * 16 * LDSM + ks * 16) * 2);
#pragma unroll
            for (int mt = 0; mt < 4; mt++)
#pragma unroll
                for (int nt = 0; nt < 4; nt++)
                    mma_bf16(acc[mt][nt], af[mt],
                             bf[nt >> 1][nt & 1], bf[nt >> 1][(nt & 1) + 2]);
        }
        // prefetch stage it+STAGES-1
        const int nxt = it + STAGES - 1;
        if (nxt < KT) {
            const int sn = nxt % STAGES;
            const int k0 = nxt * BK;
            cp16(sA0 + sn * TSTG * 2, Ag0 + k0);
            cp16(sA1 + sn * TSTG * 2, Ag1 + k0);
            cp16(sB0 + sn * TSTG * 2, Bg0 + k0);
            cp16(sB1 + sn * TSTG * 2, Bg1 + k0);
        }
        cp_commit();
    }

    // epilogue: direct fp32 stores (float2 per fragment row-half)
    const int rbase = m0 + wm + (lane >> 2);
    const int cbase = n0 + wn + (lane & 3) * 2;
#pragma unroll
    for (int mt = 0; mt < 4; mt++) {
#pragma unroll
        for (int nt = 0; nt < 4; nt++) {
            float* p0 = C + (size_t)(rbase + mt * 16) * ldc + cbase + nt * 8;
            float* p1 = p0 + 8 * ldc;
            *(float2*)p0 = make_float2(acc[mt][nt][0], acc[mt][nt][1]);
            *(float2*)p1 = make_float2(acc[mt][nt][2], acc[mt][nt][3]);
        }
    }
}

// ---------------------------------------------------------------------------
// RoPE (interleaved-pair), in-place on the 4 live heads of qh and kh.
// ---------------------------------------------------------------------------
__global__ void rope_kernel(float* __restrict__ qh, float* __restrict__ kh)
{
    int idx  = blockIdx.x * blockDim.x + threadIdx.x;
    int pair = idx & 63;
    int h    = (idx >> 6) & 3;
    int m    = idx >> 8;
    int s    = m & (S_LEN - 1);

    float freq = (float)exp(-(double)(2 * pair) * (1.0 / 128.0) * 9.210340371976184);
    float ang  = (float)s * freq;
    float c, sn;
    sincosf(ang, &sn, &c);

    size_t off = (size_t)m * D_AUG + h * 128 + 2 * pair;
    float q1 = qh[off], q2 = qh[off + 1];
    qh[off]     = q1 * c - q2 * sn;
    qh[off + 1] = q1 * sn + q2 * c;
    float k1 = kh[off], k2 = kh[off + 1];
    kh[off]     = k1 * c - k2 * sn;
    kh[off + 1] = k1 * sn + k2 * c;
}

// ---------------------------------------------------------------------------
// Flash attention, fp32, causal, per (batch, head 0..3). (unchanged)
// ---------------------------------------------------------------------------
__global__ __launch_bounds__(256)
void flash_kernel(const float* __restrict__ QH, const float* __restrict__ KH,
                  const float* __restrict__ VH, float* __restrict__ OUT)
{
    extern __shared__ float sm[];
    float* Qs  = sm;
    float* KVs = sm + 8192;
    float* Ps  = sm + 16384;

    const int qb = blockIdx.x;
    const int bh = blockIdx.y;
    const size_t base = (size_t)(bh >> 2) * S_LEN * D_AUG + (size_t)(bh & 3) * 128;
    const float* Qg = QH + base;
    const float* Kg = KH + base;
    const float* Vg = VH + base;
    float*       Og = OUT + base;

    const int tid = threadIdx.x;
    const int tx = tid & 15, ty = tid >> 4;
    const float qscale = 0.08838834764831845f;

    for (int idx = tid; idx < 64 * 32; idx += 256) {
        int r = idx >> 5, c4 = (idx & 31) * 4;
        float4 v = *(const float4*)(Qg + (size_t)(qb * 64 + r) * D_AUG + c4);
        Qs[(c4 + 0) * 64 + r] = v.x * qscale;
        Qs[(c4 + 1) * 64 + r] = v.y * qscale;
        Qs[(c4 + 2) * 64 + r] = v.z * qscale;
        Qs[(c4 + 3) * 64 + r] = v.w * qscale;
    }

    float m_i[4], l_i[4], o[4][8];
#pragma unroll
    for (int i = 0; i < 4; i++) { m_i[i] = -INFINITY; l_i[i] = 0.f; }
#pragma unroll
    for (int i = 0; i < 4; i++)
#pragma unroll
        for (int j = 0; j < 8; j++) o[i][j] = 0.f;

    for (int jb = 0; jb <= qb; jb++) {
        __syncthreads();
        for (int idx = tid; idx < 64 * 32; idx += 256) {
            int r = idx >> 5, c4 = (idx & 31) * 4;
            float4 v = *(const float4*)(Kg + (size_t)(jb * 64 + r) * D_AUG + c4);
            KVs[(c4 + 0) * 64 + r] = v.x;
            KVs[(c4 + 1) * 64 + r] = v.y;
            KVs[(c4 + 2) * 64 + r] = v.z;
            KVs[(c4 + 3) * 64 + r] = v.w;
        }
        __syncthreads();

        float sc[4][4];
#pragma unroll
        for (int i = 0; i < 4; i++)
#pragma unroll
            for (int j = 0; j < 4; j++) sc[i][j] = 0.f;
#pragma unroll 4
        for (int kk = 0; kk < 128; kk++) {
            float4 a = *(const float4*)&Qs[kk * 64 + ty * 4];
            float4 b = *(const float4*)&KVs[kk * 64 + tx * 4];
            float aa[4] = {a.x, a.y, a.z, a.w};
            float bb[4] = {b.x, b.y, b.z, b.w};
#pragma unroll
            for (int i = 0; i < 4; i++)
#pragma unroll
                for (int j = 0; j < 4; j++)
                    sc[i][j] = fmaf(aa[i], bb[j], sc[i][j]);
        }

        if (jb == qb) {
#pragma unroll
            for (int i = 0; i < 4; i++)
#pragma unroll
                for (int j = 0; j < 4; j++)
                    if (tx * 4 + j > ty * 4 + i) sc[i][j] = -1e30f;
        }

        float scl[4];
#pragma unroll
        for (int i = 0; i < 4; i++) {
            float mt = fmaxf(fmaxf(sc[i][0], sc[i][1]), fmaxf(sc[i][2], sc[i][3]));
#pragma unroll
            for (int off = 1; off < 16; off <<= 1)
                mt = fmaxf(mt, __shfl_xor_sync(0xffffffffu, mt, off));
            float mnew = fmaxf(m_i[i], mt);
            scl[i] = expf(m_i[i] - mnew);
            float s0 = 0.f;
#pragma unroll
            for (int j = 0; j < 4; j++) {
                float p = expf(sc[i][j] - mnew);
                sc[i][j] = p;
                s0 += p;
            }
#pragma unroll
            for (int off = 1; off < 16; off <<= 1)
                s0 += __shfl_xor_sync(0xffffffffu, s0, off);
            l_i[i] = l_i[i] * scl[i] + s0;
            m_i[i] = mnew;
        }
#pragma unroll
        for (int i = 0; i < 4; i++)
#pragma unroll
            for (int j = 0; j < 8; j++) o[i][j] *= scl[i];

        __syncthreads();
#pragma unroll
        for (int i = 0; i < 4; i++)
#pragma unroll
            for (int j = 0; j < 4; j++)
                Ps[(tx * 4 + j) * 64 + ty * 4 + i] = sc[i][j];
        for (int idx = tid; idx < 64 * 32; idx += 256) {
            int c = idx >> 5, d4 = (idx & 31) * 4;
            *(float4*)&KVs[c * 128 + d4] =
                *(const float4*)(Vg + (size_t)(jb * 64 + c) * D_AUG + d4);
        }
        __syncthreads();

#pragma unroll 2
        for (int c = 0; c < 64; c++) {
            float4 p  = *(const float4*)&Ps[c * 64 + ty * 4];
            float4 v0 = *(const float4*)&KVs[c * 128 + tx * 4];
            float4 v1 = *(const float4*)&KVs[c * 128 + 64 + tx * 4];
            float pp[4] = {p.x, p.y, p.z, p.w};
            float va[4] = {v0.x, v0.y, v0.z, v0.w};
            float vb[4] = {v1.x, v1.y, v1.z, v1.w};
#pragma unroll
            for (int i = 0; i < 4; i++) {
#pragma unroll
                for (int j = 0; j < 4; j++) {
                    o[i][j]     = fmaf(pp[i], va[j], o[i][j]);
                    o[i][j + 4] = fmaf(pp[i], vb[j], o[i][j + 4]);
                }
            }
        }
    }

#pragma unroll
    for (int i = 0; i < 4; i++) {
        float inv = 1.0f / l_i[i];
        float* orow = Og + (size_t)(qb * 64 + ty * 4 + i) * D_AUG;
        *(float4*)(orow + tx * 4) =
            make_float4(o[i][0] * inv, o[i][1] * inv, o[i][2] * inv, o[i][3] * inv);
        *(float4*)(orow + 64 + tx * 4) =
            make_float4(o[i][4] * inv, o[i][5] * inv, o[i][6] * inv, o[i][7] * inv);
    }
}

// ---------------------------------------------------------------------------
// Host side
// ---------------------------------------------------------------------------
extern "C" void kernel_launch(void* const* d_in, const int* in_sizes, int n_in,
                              void* d_out, int out_size)
{
    const float* q  = (const float*)d_in[0];
    const float* k  = (const float*)d_in[1];
    const float* v  = (const float*)d_in[2];
    const float* Wq = (const float*)d_in[3];
    const float* Wk = (const float*)d_in[4];
    const float* Wv = (const float*)d_in[5];
    const float* Wo = (const float*)d_in[6];
    float* out = (float*)d_out;

    float *qh, *kh, *vh, *attn;
    cudaGetSymbolAddress((void**)&qh,   g_qh);
    cudaGetSymbolAddress((void**)&kh,   g_kh);
    cudaGetSymbolAddress((void**)&vh,   g_vh);
    cudaGetSymbolAddress((void**)&attn, g_attn);
    __nv_bfloat16 *qs, *ks, *vs, *ats, *wqs, *wks, *wvs, *wos;
    cudaGetSymbolAddress((void**)&qs,  g_q_s);
    cudaGetSymbolAddress((void**)&ks,  g_k_s);
    cudaGetSymbolAddress((void**)&vs,  g_v_s);
    cudaGetSymbolAddress((void**)&ats, g_attn_s);
    cudaGetSymbolAddress((void**)&wqs, g_Wq_s);
    cudaGetSymbolAddress((void**)&wks, g_Wk_s);
    cudaGetSymbolAddress((void**)&wvs, g_Wv_s);
    cudaGetSymbolAddress((void**)&wos, g_Wo_s);

    cudaFuncSetAttribute(gemm_hmma, cudaFuncAttributeMaxDynamicSharedMemorySize, GEMM_SMEM);
    cudaFuncSetAttribute(flash_kernel, cudaFuncAttributeMaxDynamicSharedMemorySize, 81920);

    auto blocks = [](long long n) { return (unsigned)((n + 255) / 256); };

    // 1) split-precision conversions (A-side: [hi|hi|lo], B-side: [hi|lo|hi])
    split3_kernel<<<blocks(4096LL * 384), 256>>>(q,         D_EMB, qs,  D_EMB, 4096, 0);
    split3_kernel<<<blocks(4096LL * 384), 256>>>(k,         D_EMB, ks,  D_EMB, 4096, 0);
    split3_kernel<<<blocks(4096LL * 128), 256>>>(v + D_AUG, D_EMB, vs,  D_AUG, 4096, 0);
    split3_kernel<<<blocks(512LL * 384),  256>>>(Wq,        D_EMB, wqs, D_EMB, 512, 1);
    split3_kernel<<<blocks(512LL * 384),  256>>>(Wk,        D_EMB, wks, D_EMB, 512, 1);
    split3_kernel<<<blocks(512LL * 128),  256>>>(Wv,        D_AUG, wvs, D_AUG, 512, 1);
    split3_kernel<<<blocks(1536LL * 128), 256>>>(Wo,        D_EMB, wos, D_AUG, 1536, 1);

    // 2) projections on HMMA tensor cores (exact split-bf16)
    // qh[:, :512] = q @ Wq[:512]^T
    gemm_hmma<<<dim3(4, 32), 256, GEMM_SMEM>>>(qs, wqs, qh, 3 * D_EMB, D_AUG);
    gemm_hmma<<<dim3(4, 32), 256, GEMM_SMEM>>>(ks, wks, kh, 3 * D_EMB, D_AUG);
    gemm_hmma<<<dim3(4, 32), 256, GEMM_SMEM>>>(vs, wvs, vh, 3 * D_AUG, D_AUG);

    // 3) RoPE on the 4 live heads
    rope_kernel<<<4096, 256>>>(qh, kh);

    // 4) flash attention (fp32 SIMT)
    flash_kernel<<<dim3(32, 8), 256, 81920>>>(qh, kh, vh, attn);

    // 5) output projection: out = attn[:, :512] @ Wo[:, :512]^T
    split3_kernel<<<blocks(4096LL * 128), 256>>>(attn, D_AUG, ats, D_AUG, 4096, 0);
    gemm_hmma<<<dim3(12, 32), 256, GEMM_SMEM>>>(ats, wos, out, 3 * D_AUG, D_EMB);
}

// round 6
// speedup vs baseline: 3.1525x; 2.4498x over previous
#include <cuda_runtime.h>
#include <cuda_bf16.h>
#include <math.h>
#include <stdint.h>

#define BS_TOT 4096
#define S_LEN  2048
#define D_EMB  1536
#define D_AUG  512

// ---------------- device scratch ----------------
__device__ float g_qh[BS_TOT * D_AUG];
__device__ float g_kh[BS_TOT * D_AUG];
__device__ float g_vh[BS_TOT * D_AUG];
__device__ float g_rope[2 * S_LEN * 64];   // cos | sin

// split-bf16 GEMM operands: A-side [hi|hi|lo], B-side [hi|lo|hi]
__device__ __align__(128) __nv_bfloat16 g_q_s   [BS_TOT * 3 * D_EMB];
__device__ __align__(128) __nv_bfloat16 g_k_s   [BS_TOT * 3 * D_EMB];
__device__ __align__(128) __nv_bfloat16 g_v_s   [BS_TOT * 3 * D_AUG];
__device__ __align__(128) __nv_bfloat16 g_attn_s[BS_TOT * 3 * D_AUG];
__device__ __align__(128) __nv_bfloat16 g_Wq_s  [D_AUG * 3 * D_EMB];
__device__ __align__(128) __nv_bfloat16 g_Wk_s  [D_AUG * 3 * D_EMB];
__device__ __align__(128) __nv_bfloat16 g_Wv_s  [D_AUG * 3 * D_AUG];
__device__ __align__(128) __nv_bfloat16 g_Wo_s  [D_EMB * 3 * D_AUG];

// flash operand planes: q/k [bh][s][128]; vt [bh][128][s]
__device__ __align__(128) __nv_bfloat16 g_qhi[8 * S_LEN * 128];
__device__ __align__(128) __nv_bfloat16 g_qlo[8 * S_LEN * 128];
__device__ __align__(128) __nv_bfloat16 g_khi[8 * S_LEN * 128];
__device__ __align__(128) __nv_bfloat16 g_klo[8 * S_LEN * 128];
__device__ __align__(128) __nv_bfloat16 g_vthi[8 * 128 * S_LEN];
__device__ __align__(128) __nv_bfloat16 g_vtlo[8 * 128 * S_LEN];

// single shared dynamic-smem declaration used by all kernels
extern __shared__ __align__(128) char dynsmem[];

// ---------------------------------------------------------------------------
__device__ __forceinline__ uint32_t smem_u32(const void* p) {
    uint32_t a;
    asm("{ .reg .u64 t; cvta.to.shared.u64 t, %1; cvt.u32.u64 %0, t; }" : "=r"(a) : "l"(p));
    return a;
}
__device__ __forceinline__ void cp16(uint32_t saddr, const void* gaddr) {
    asm volatile("cp.async.cg.shared.global [%0], [%1], 16;" :: "r"(saddr), "l"(gaddr) : "memory");
}
__device__ __forceinline__ void cp_commit() {
    asm volatile("cp.async.commit_group;" ::: "memory");
}
template <int N>
__device__ __forceinline__ void cp_wait() {
    asm volatile("cp.async.wait_group %0;" :: "n"(N) : "memory");
}
__device__ __forceinline__ void ldmx4(uint32_t* r, uint32_t addr) {
    asm volatile("ldmatrix.sync.aligned.m8n8.x4.shared.b16 {%0,%1,%2,%3}, [%4];"
                 : "=r"(r[0]), "=r"(r[1]), "=r"(r[2]), "=r"(r[3]) : "r"(addr));
}
__device__ __forceinline__ void mma_bf16(float* c, const uint32_t* a, uint32_t b0, uint32_t b1) {
    asm volatile(
        "mma.sync.aligned.m16n8k16.row.col.f32.bf16.bf16.f32 "
        "{%0,%1,%2,%3}, {%4,%5,%6,%7}, {%8,%9}, {%0,%1,%2,%3};"
        : "+f"(c[0]), "+f"(c[1]), "+f"(c[2]), "+f"(c[3])
        : "r"(a[0]), "r"(a[1]), "r"(a[2]), "r"(a[3]), "r"(b0), "r"(b1));
}
__device__ __forceinline__ float ex2(float x) {
    float y; asm("ex2.approx.f32 %0, %1;" : "=f"(y) : "f"(x)); return y;
}

// ---------------------------------------------------------------------------
// split3: dst rows length 3K; bmode=0: [hi|hi|lo], bmode=1: [hi|lo|hi]
// ---------------------------------------------------------------------------
__global__ void split3_kernel(const float* __restrict__ src, int sld,
                              __nv_bfloat16* __restrict__ dst, int K, int rows, int bmode)
{
    int K4 = K >> 2;
    int i = blockIdx.x * blockDim.x + threadIdx.x;
    if (i >= rows * K4) return;
    int r = i / K4, c4 = (i - r * K4) << 2;
    float4 x = *(const float4*)(src + (size_t)r * sld + c4);
    float xs[4] = {x.x, x.y, x.z, x.w};
    __nv_bfloat162 h0, h1, l0, l1;
    __nv_bfloat16 h[4], l[4];
#pragma unroll
    for (int j = 0; j < 4; j++) {
        h[j] = __float2bfloat16(xs[j]);
        l[j] = __float2bfloat16(xs[j] - __bfloat162float(h[j]));
    }
    h0.x = h[0]; h0.y = h[1]; h1.x = h[2]; h1.y = h[3];
    l0.x = l[0]; l0.y = l[1]; l1.x = l[2]; l1.y = l[3];
    __nv_bfloat16* d = dst + (size_t)r * 3 * K + c4;
    *(__nv_bfloat162*)(d)     = h0;  *(__nv_bfloat162*)(d + 2)     = h1;
    if (bmode == 0) {
        *(__nv_bfloat162*)(d + K)     = h0;  *(__nv_bfloat162*)(d + K + 2)     = h1;
        *(__nv_bfloat162*)(d + 2 * K) = l0;  *(__nv_bfloat162*)(d + 2 * K + 2) = l1;
    } else {
        *(__nv_bfloat162*)(d + K)     = l0;  *(__nv_bfloat162*)(d + K + 2)     = l1;
        *(__nv_bfloat162*)(d + 2 * K) = h0;  *(__nv_bfloat162*)(d + 2 * K + 2) = h1;
    }
}

// ---------------------------------------------------------------------------
// HMMA GEMM: C[M,N] = A[M,K3] @ B[N,K3]^T
// ---------------------------------------------------------------------------
#define BM 128
#define BN 128
#define BK 32
#define LDSM 40
#define STAGES 3
#define TSTG (BM * LDSM)
#define GEMM_SMEM (2 * STAGES * TSTG * 2)

__global__ void __launch_bounds__(256, 1)
gemm_hmma(const __nv_bfloat16* __restrict__ A, const __nv_bfloat16* __restrict__ B,
          float* __restrict__ C, int K3, int ldc)
{
    __nv_bfloat16* As = (__nv_bfloat16*)dynsmem;
    __nv_bfloat16* Bs = As + STAGES * TSTG;

    const int tid  = threadIdx.x;
    const int wid  = tid >> 5, lane = tid & 31;
    const int m0   = blockIdx.y * BM, n0 = blockIdx.x * BN;
    const int wm   = (wid >> 2) * 64;
    const int wn   = (wid & 3) * 32;

    const int lrow0 = tid >> 2,         lq0 = tid & 3;
    const int lrow1 = (tid + 256) >> 2, lq1 = (tid + 256) & 3;

    const __nv_bfloat16* Ag0 = A + (size_t)(m0 + lrow0) * K3 + lq0 * 8;
    const __nv_bfloat16* Ag1 = A + (size_t)(m0 + lrow1) * K3 + lq1 * 8;
    const __nv_bfloat16* Bg0 = B + (size_t)(n0 + lrow0) * K3 + lq0 * 8;
    const __nv_bfloat16* Bg1 = B + (size_t)(n0 + lrow1) * K3 + lq1 * 8;
    const uint32_t sA0 = smem_u32(As) + (lrow0 * LDSM + lq0 * 8) * 2;
    const uint32_t sA1 = smem_u32(As) + (lrow1 * LDSM + lq1 * 8) * 2;
    const uint32_t sB0 = smem_u32(Bs) + (lrow0 * LDSM + lq0 * 8) * 2;
    const uint32_t sB1 = smem_u32(Bs) + (lrow1 * LDSM + lq1 * 8) * 2;

    const int KT = K3 / BK;

    float acc[4][4][4];
#pragma unroll
    for (int i = 0; i < 4; i++)
#pragma unroll
        for (int j = 0; j < 4; j++)
#pragma unroll
            for (int t = 0; t < 4; t++) acc[i][j][t] = 0.f;

    const uint32_t als = smem_u32(As) + ((wm + (lane & 15)) * LDSM + (lane >> 4) * 8) * 2;
    const uint32_t bls = smem_u32(Bs) + ((wn + (lane & 15)) * LDSM + (lane >> 4) * 8) * 2;

#pragma unroll
    for (int s = 0; s < STAGES - 1; s++) {
        int k0 = s * BK;
        cp16(sA0 + s * TSTG * 2, Ag0 + k0);
        cp16(sA1 + s * TSTG * 2, Ag1 + k0);
        cp16(sB0 + s * TSTG * 2, Bg0 + k0);
        cp16(sB1 + s * TSTG * 2, Bg1 + k0);
        cp_commit();
    }

    for (int it = 0; it < KT; it++) {
        cp_wait<STAGES - 2>();
        __syncthreads();
        const int sc = it % STAGES;
        const uint32_t abase = als + sc * TSTG * 2;
        const uint32_t bbase = bls + sc * TSTG * 2;
#pragma unroll
        for (int ks = 0; ks < 2; ks++) {
            uint32_t af[4][4], bf[2][4];
#pragma unroll
            for (int mt = 0; mt < 4; mt++)
                ldmx4(af[mt], abase + (mt * 16 * LDSM + ks * 16) * 2);
#pragma unroll
            for (int nt2 = 0; nt2 < 2; nt2++)
                ldmx4(bf[nt2], bbase + (nt2 * 16 * LDSM + ks * 16) * 2);
#pragma unroll
            for (int mt = 0; mt < 4; mt++)
#pragma unroll
                for (int nt = 0; nt < 4; nt++)
                    mma_bf16(acc[mt][nt], af[mt],
                             bf[nt >> 1][nt & 1], bf[nt >> 1][(nt & 1) + 2]);
        }
        const int nxt = it + STAGES - 1;
        if (nxt < KT) {
            const int sn = nxt % STAGES;
            const int k0 = nxt * BK;
            cp16(sA0 + sn * TSTG * 2, Ag0 + k0);
            cp16(sA1 + sn * TSTG * 2, Ag1 + k0);
            cp16(sB0 + sn * TSTG * 2, Bg0 + k0);
            cp16(sB1 + sn * TSTG * 2, Bg1 + k0);
        }
        cp_commit();
    }

    const int rbase = m0 + wm + (lane >> 2);
    const int cbase = n0 + wn + (lane & 3) * 2;
#pragma unroll
    for (int mt = 0; mt < 4; mt++) {
#pragma unroll
        for (int nt = 0; nt < 4; nt++) {
            float* p0 = C + (size_t)(rbase + mt * 16) * ldc + cbase + nt * 8;
            float* p1 = p0 + 8 * ldc;
            *(float2*)p0 = make_float2(acc[mt][nt][0], acc[mt][nt][1]);
            *(float2*)p1 = make_float2(acc[mt][nt][2], acc[mt][nt][3]);
        }
    }
}

// ---------------------------------------------------------------------------
// RoPE table: cos/sin for (s, pair)
// ---------------------------------------------------------------------------
__global__ void rope_table_kernel(float* __restrict__ tab)
{
    int idx = blockIdx.x * blockDim.x + threadIdx.x;   // 2048*64
    if (idx >= S_LEN * 64) return;
    int pair = idx & 63, s = idx >> 6;
    float freq = (float)exp(-(double)(2 * pair) * (1.0 / 128.0) * 9.210340371976184);
    float ang  = (float)s * freq;
    tab[idx]              = cosf(ang);
    tab[S_LEN * 64 + idx] = sinf(ang);
}

// ---------------------------------------------------------------------------
// RoPE + split-bf16 plane emission. q scaled by 1/sqrt(128).
// ---------------------------------------------------------------------------
__global__ void rope_split_kernel(const float* __restrict__ qh, const float* __restrict__ kh,
                                  const float* __restrict__ tab,
                                  __nv_bfloat16* __restrict__ qhi, __nv_bfloat16* __restrict__ qlo,
                                  __nv_bfloat16* __restrict__ khi, __nv_bfloat16* __restrict__ klo)
{
    int idx  = blockIdx.x * blockDim.x + threadIdx.x;  // 8*2048*64
    int pair = idx & 63;
    int s    = (idx >> 6) & (S_LEN - 1);
    int bh   = idx >> 17;
    int b = bh >> 2, h = bh & 3;

    float c  = tab[s * 64 + pair];
    float sn = tab[S_LEN * 64 + s * 64 + pair];

    size_t src = (size_t)(b * S_LEN + s) * D_AUG + h * 128 + 2 * pair;
    size_t dst = (size_t)bh * S_LEN * 128 + (size_t)s * 128 + 2 * pair;
    const float qscale = 0.08838834764831845f;

    float q1 = qh[src], q2 = qh[src + 1];
    float qa = (q1 * c - q2 * sn) * qscale;
    float qb = (q1 * sn + q2 * c) * qscale;
    __nv_bfloat16 ha = __float2bfloat16(qa), hb = __float2bfloat16(qb);
    __nv_bfloat162 hv; hv.x = ha; hv.y = hb;
    __nv_bfloat162 lv;
    lv.x = __float2bfloat16(qa - __bfloat162float(ha));
    lv.y = __float2bfloat16(qb - __bfloat162float(hb));
    *(__nv_bfloat162*)(qhi + dst) = hv;
    *(__nv_bfloat162*)(qlo + dst) = lv;

    float k1 = kh[src], k2 = kh[src + 1];
    float ka = k1 * c - k2 * sn;
    float kb = k1 * sn + k2 * c;
    ha = __float2bfloat16(ka); hb = __float2bfloat16(kb);
    hv.x = ha; hv.y = hb;
    lv.x = __float2bfloat16(ka - __bfloat162float(ha));
    lv.y = __float2bfloat16(kb - __bfloat162float(hb));
    *(__nv_bfloat162*)(khi + dst) = hv;
    *(__nv_bfloat162*)(klo + dst) = lv;
}

// ---------------------------------------------------------------------------
// V transpose + split: vh [(b,s)][(h,d)] fp32 -> vt planes [bh][d][s] bf16
// ---------------------------------------------------------------------------
__global__ void vt_split_kernel(const float* __restrict__ vh,
                                __nv_bfloat16* __restrict__ vthi, __nv_bfloat16* __restrict__ vtlo)
{
    __shared__ float tile[32][33];
    int bh = blockIdx.z, b = bh >> 2, h = bh & 3;
    int tx = threadIdx.x, ty = threadIdx.y;
    int s_in = blockIdx.x * 32 + ty;
    int d_in = blockIdx.y * 32 + tx;
    tile[ty][tx] = vh[(size_t)(b * S_LEN + s_in) * D_AUG + h * 128 + d_in];
    __syncthreads();
    int d_out = blockIdx.y * 32 + ty;
    int s_out = blockIdx.x * 32 + tx;
    float v = tile[tx][ty];
    __nv_bfloat16 hi = __float2bfloat16(v);
    size_t dst = (size_t)bh * 128 * S_LEN + (size_t)d_out * S_LEN + s_out;
    vthi[dst] = hi;
    vtlo[dst] = __float2bfloat16(v - __bfloat162float(hi));
}

// ---------------------------------------------------------------------------
// HMMA flash attention, causal, split-bf16 QK^T and P.V.
// Br=Bc=64. 8 warps: mw=wid>>1 (16 rows), nw=wid&1.
// CTA pairing: blockIdx.x=p handles qblocks {p, 31-p} -> 33 iters each CTA.
// ---------------------------------------------------------------------------
#define FB_QHI 0
#define FB_QLO 17408
#define FB_KHI 34816
#define FB_KLO 52224
#define FB_VHI 69632
#define FB_VLO 88064
#define FB_PHI 106496
#define FB_PLO 115712
#define FB_RED 124928
#define FB_SMEM 125952
#define L2E 1.4426950408889634f

__global__ void __launch_bounds__(256, 1)
flash_hmma(const __nv_bfloat16* __restrict__ qhi, const __nv_bfloat16* __restrict__ qlo,
           const __nv_bfloat16* __restrict__ khi, const __nv_bfloat16* __restrict__ klo,
           const __nv_bfloat16* __restrict__ vthi, const __nv_bfloat16* __restrict__ vtlo,
           __nv_bfloat16* __restrict__ attn_s)
{
    char* fsm = dynsmem;
    const uint32_t sb = smem_u32(fsm);
    float* red = (float*)(fsm + FB_RED);     // [0:128) max, [128:256) sum

    const int tid  = threadIdx.x;
    const int lane = tid & 31;
    const int wid  = tid >> 5;
    const int mw   = wid >> 1;
    const int nw   = wid & 1;
    const int bh   = blockIdx.y;
    const int b    = bh >> 2, hh = bh & 3;

    const size_t qkplane = (size_t)bh * S_LEN * 128;
    const size_t vplane  = (size_t)bh * 128 * S_LEN;

    const uint32_t aoffQ = (mw * 16 + (lane & 15)) * 272 + (lane >> 4) * 16;
    const uint32_t boffK = (nw * 32 + (lane & 15)) * 272 + (lane >> 4) * 16;
    const uint32_t aoffP = (mw * 16 + (lane & 15)) * 144 + (lane >> 4) * 16;
    const uint32_t boffV = (nw * 64 + (lane & 15)) * 144 + (lane >> 4) * 16;

    const int r0 = lane >> 2;
    const int c2 = (lane & 3) * 2;
    const int rloc0 = mw * 16 + r0;
    const int rloc1 = rloc0 + 8;

    for (int qq = 0; qq < 2; qq++) {
        const int qb = qq ? 31 - (int)blockIdx.x : (int)blockIdx.x;

        __syncthreads();
        {
            const __nv_bfloat16* srcs[2] = {qhi + qkplane + (size_t)qb * 64 * 128,
                                            qlo + qkplane + (size_t)qb * 64 * 128};
#pragma unroll
            for (int p = 0; p < 2; p++)
#pragma unroll
                for (int i = 0; i < 4; i++) {
                    int c = tid + i * 256;
                    int r = c >> 4, qx = c & 15;
                    cp16(sb + FB_QHI + p * 17408 + r * 272 + qx * 16,
                         srcs[p] + (size_t)r * 128 + qx * 8);
                }
            cp_commit();
        }
        cp_wait<0>();
        __syncthreads();

        float m0 = -1e30f, m1 = -1e30f, l0 = 0.f, l1 = 0.f;
        float o[8][4];
#pragma unroll
        for (int f = 0; f < 8; f++)
#pragma unroll
            for (int e = 0; e < 4; e++) o[f][e] = 0.f;

        for (int jb = 0; jb <= qb; jb++) {
            __syncthreads();
            {
                const __nv_bfloat16* ks[2] = {khi + qkplane + (size_t)jb * 64 * 128,
                                              klo + qkplane + (size_t)jb * 64 * 128};
#pragma unroll
                for (int p = 0; p < 2; p++)
#pragma unroll
                    for (int i = 0; i < 4; i++) {
                        int c = tid + i * 256;
                        int r = c >> 4, qx = c & 15;
                        cp16(sb + FB_KHI + p * 17408 + r * 272 + qx * 16,
                             ks[p] + (size_t)r * 128 + qx * 8);
                    }
                const __nv_bfloat16* vs[2] = {vthi + vplane + jb * 64,
                                              vtlo + vplane + jb * 64};
#pragma unroll
                for (int p = 0; p < 2; p++)
#pragma unroll
                    for (int i = 0; i < 4; i++) {
                        int c = tid + i * 256;
                        int r = c >> 3, qx = c & 7;
                        cp16(sb + FB_VHI + p * 18432 + r * 144 + qx * 16,
                             vs[p] + (size_t)r * S_LEN + qx * 8);
                    }
                cp_commit();
            }
            cp_wait<0>();
            __syncthreads();

            float sacc[4][4];
#pragma unroll
            for (int f = 0; f < 4; f++)
#pragma unroll
                for (int e = 0; e < 4; e++) sacc[f][e] = 0.f;

            const uint32_t aB[3] = {sb + FB_QHI, sb + FB_QHI, sb + FB_QLO};
            const uint32_t bB[3] = {sb + FB_KHI, sb + FB_KLO, sb + FB_KHI};
#pragma unroll
            for (int ps = 0; ps < 3; ps++) {
                const uint32_t ab = aB[ps] + aoffQ;
                const uint32_t bb0 = bB[ps] + boffK;
                const uint32_t bb1 = bb0 + 16 * 272;
#pragma unroll
                for (int ks = 0; ks < 8; ks++) {
                    uint32_t a[4], q0[4], q1[4];
                    ldmx4(a,  ab  + ks * 32);
                    ldmx4(q0, bb0 + ks * 32);
                    ldmx4(q1, bb1 + ks * 32);
                    mma_bf16(sacc[0], a, q0[0], q0[2]);
                    mma_bf16(sacc[1], a, q0[1], q0[3]);
                    mma_bf16(sacc[2], a, q1[0], q1[2]);
                    mma_bf16(sacc[3], a, q1[1], q1[3]);
                }
            }

            if (jb == qb) {
#pragma unroll
                for (int f = 0; f < 4; f++) {
                    int colb = nw * 32 + (f >> 1) * 16 + (f & 1) * 8 + c2;
#pragma unroll
                    for (int e = 0; e < 4; e++) {
                        int row = mw * 16 + r0 + ((e >> 1) << 3);
                        int col = colb + (e & 1);
                        if (col > row) sacc[f][e] = -1e30f;
                    }
                }
            }

            float pm0 = -1e30f, pm1 = -1e30f;
#pragma unroll
            for (int f = 0; f < 4; f++) {
                pm0 = fmaxf(pm0, fmaxf(sacc[f][0], sacc[f][1]));
                pm1 = fmaxf(pm1, fmaxf(sacc[f][2], sacc[f][3]));
            }
            pm0 = fmaxf(pm0, __shfl_xor_sync(0xffffffffu, pm0, 1));
            pm0 = fmaxf(pm0, __shfl_xor_sync(0xffffffffu, pm0, 2));
            pm1 = fmaxf(pm1, __shfl_xor_sync(0xffffffffu, pm1, 1));
            pm1 = fmaxf(pm1, __shfl_xor_sync(0xffffffffu, pm1, 2));
            if ((lane & 3) == 0) {
                red[nw * 64 + rloc0] = pm0;
                red[nw * 64 + rloc1] = pm1;
            }
            __syncthreads();
            float rm0 = fmaxf(red[rloc0], red[64 + rloc0]);
            float rm1 = fmaxf(red[rloc1], red[64 + rloc1]);
            float mn0 = fmaxf(m0, rm0), mn1 = fmaxf(m1, rm1);
            float scl0 = ex2((m0 - mn0) * L2E);
            float scl1 = ex2((m1 - mn1) * L2E);

            float ts0 = 0.f, ts1 = 0.f;
#pragma unroll
            for (int f = 0; f < 4; f++) {
                int col = nw * 32 + (f >> 1) * 16 + (f & 1) * 8 + c2;
                float p00 = ex2((sacc[f][0] - mn0) * L2E);
                float p01 = ex2((sacc[f][1] - mn0) * L2E);
                float p10 = ex2((sacc[f][2] - mn1) * L2E);
                float p11 = ex2((sacc[f][3] - mn1) * L2E);
                ts0 += p00 + p01;
                ts1 += p10 + p11;
                __nv_bfloat16 h00 = __float2bfloat16(p00), h01 = __float2bfloat16(p01);
                __nv_bfloat16 h10 = __float2bfloat16(p10), h11 = __float2bfloat16(p11);
                __nv_bfloat162 hv, lv;
                hv.x = h00; hv.y = h01;
                lv.x = __float2bfloat16(p00 - __bfloat162float(h00));
                lv.y = __float2bfloat16(p01 - __bfloat162float(h01));
                *(__nv_bfloat162*)(fsm + FB_PHI + rloc0 * 144 + col * 2) = hv;
                *(__nv_bfloat162*)(fsm + FB_PLO + rloc0 * 144 + col * 2) = lv;
                hv.x = h10; hv.y = h11;
                lv.x = __float2bfloat16(p10 - __bfloat162float(h10));
                lv.y = __float2bfloat16(p11 - __bfloat162float(h11));
                *(__nv_bfloat162*)(fsm + FB_PHI + rloc1 * 144 + col * 2) = hv;
                *(__nv_bfloat162*)(fsm + FB_PLO + rloc1 * 144 + col * 2) = lv;
            }
            ts0 += __shfl_xor_sync(0xffffffffu, ts0, 1);
            ts0 += __shfl_xor_sync(0xffffffffu, ts0, 2);
            ts1 += __shfl_xor_sync(0xffffffffu, ts1, 1);
            ts1 += __shfl_xor_sync(0xffffffffu, ts1, 2);
            if ((lane & 3) == 0) {
                red[128 + nw * 64 + rloc0] = ts0;
                red[128 + nw * 64 + rloc1] = ts1;
            }
            __syncthreads();
            l0 = l0 * scl0 + red[128 + rloc0] + red[128 + 64 + rloc0];
            l1 = l1 * scl1 + red[128 + rloc1] + red[128 + 64 + rloc1];
            m0 = mn0; m1 = mn1;
#pragma unroll
            for (int f = 0; f < 8; f++) {
                o[f][0] *= scl0; o[f][1] *= scl0;
                o[f][2] *= scl1; o[f][3] *= scl1;
            }

            const uint32_t aP[3] = {sb + FB_PHI, sb + FB_PHI, sb + FB_PLO};
            const uint32_t bV[3] = {sb + FB_VHI, sb + FB_VLO, sb + FB_VHI};
#pragma unroll
            for (int ps = 0; ps < 3; ps++) {
                const uint32_t ab = aP[ps] + aoffP;
                const uint32_t bb = bV[ps] + boffV;
#pragma unroll
                for (int ks = 0; ks < 4; ks++) {
                    uint32_t a[4];
                    ldmx4(a, ab + ks * 32);
#pragma unroll
                    for (int g2 = 0; g2 < 4; g2++) {
                        uint32_t qv[4];
                        ldmx4(qv, bb + g2 * (16 * 144) + ks * 32);
                        mma_bf16(o[g2 * 2 + 0], a, qv[0], qv[2]);
                        mma_bf16(o[g2 * 2 + 1], a, qv[1], qv[3]);
                    }
                }
            }
        }

        float inv0 = 1.0f / l0, inv1 = 1.0f / l1;
        size_t rg0 = (size_t)(b * S_LEN + qb * 64 + rloc0) * (3 * D_AUG);
        size_t rg1 = (size_t)(b * S_LEN + qb * 64 + rloc1) * (3 * D_AUG);
#pragma unroll
        for (int f = 0; f < 8; f++) {
            int col = hh * 128 + nw * 64 + (f >> 1) * 16 + (f & 1) * 8 + c2;
            float v0 = o[f][0] * inv0, v1 = o[f][1] * inv0;
            __nv_bfloat16 h0 = __float2bfloat16(v0), h1 = __float2bfloat16(v1);
            __nv_bfloat162 hv, lv;
            hv.x = h0; hv.y = h1;
            lv.x = __float2bfloat16(v0 - __bfloat162float(h0));
            lv.y = __float2bfloat16(v1 - __bfloat162float(h1));
            *(__nv_bfloat162*)(attn_s + rg0 + col)             = hv;
            *(__nv_bfloat162*)(attn_s + rg0 + col + D_AUG)     = hv;
            *(__nv_bfloat162*)(attn_s + rg0 + col + 2 * D_AUG) = lv;
            v0 = o[f][2] * inv1; v1 = o[f][3] * inv1;
            h0 = __float2bfloat16(v0); h1 = __float2bfloat16(v1);
            hv.x = h0; hv.y = h1;
            lv.x = __float2bfloat16(v0 - __bfloat162float(h0));
            lv.y = __float2bfloat16(v1 - __bfloat162float(h1));
            *(__nv_bfloat162*)(attn_s + rg1 + col)             = hv;
            *(__nv_bfloat162*)(attn_s + rg1 + col + D_AUG)     = hv;
            *(__nv_bfloat162*)(attn_s + rg1 + col + 2 * D_AUG) = lv;
        }
    }
}

// ---------------------------------------------------------------------------
extern "C" void kernel_launch(void* const* d_in, const int* in_sizes, int n_in,
                              void* d_out, int out_size)
{
    const float* q  = (const float*)d_in[0];
    const float* k  = (const float*)d_in[1];
    const float* v  = (const float*)d_in[2];
    const float* Wq = (const float*)d_in[3];
    const float* Wk = (const float*)d_in[4];
    const float* Wv = (const float*)d_in[5];
    const float* Wo = (const float*)d_in[6];
    float* out = (float*)d_out;

    float *qh, *kh, *vh, *rtab;
    cudaGetSymbolAddress((void**)&qh,   g_qh);
    cudaGetSymbolAddress((void**)&kh,   g_kh);
    cudaGetSymbolAddress((void**)&vh,   g_vh);
    cudaGetSymbolAddress((void**)&rtab, g_rope);
    __nv_bfloat16 *qs, *ks, *vs, *ats, *wqs, *wks, *wvs, *wos;
    __nv_bfloat16 *pqhi, *pqlo, *pkhi, *pklo, *pvthi, *pvtlo;
    cudaGetSymbolAddress((void**)&qs,  g_q_s);
    cudaGetSymbolAddress((void**)&ks,  g_k_s);
    cudaGetSymbolAddress((void**)&vs,  g_v_s);
    cudaGetSymbolAddress((void**)&ats, g_attn_s);
    cudaGetSymbolAddress((void**)&wqs, g_Wq_s);
    cudaGetSymbolAddress((void**)&wks, g_Wk_s);
    cudaGetSymbolAddress((void**)&wvs, g_Wv_s);
    cudaGetSymbolAddress((void**)&wos, g_Wo_s);
    cudaGetSymbolAddress((void**)&pqhi, g_qhi);
    cudaGetSymbolAddress((void**)&pqlo, g_qlo);
    cudaGetSymbolAddress((void**)&pkhi, g_khi);
    cudaGetSymbolAddress((void**)&pklo, g_klo);
    cudaGetSymbolAddress((void**)&pvthi, g_vthi);
    cudaGetSymbolAddress((void**)&pvtlo, g_vtlo);

    cudaFuncSetAttribute(gemm_hmma, cudaFuncAttributeMaxDynamicSharedMemorySize, GEMM_SMEM);
    cudaFuncSetAttribute(flash_hmma, cudaFuncAttributeMaxDynamicSharedMemorySize, FB_SMEM);

    auto blocks = [](long long n) { return (unsigned)((n + 255) / 256); };

    // Launch order chosen so launch #6 (ncu -s 5 -c 1) is gemm_hmma.
    split3_kernel<<<blocks(4096LL * 384), 256>>>(q,  D_EMB, qs,  D_EMB, 4096, 0);   // 1
    split3_kernel<<<blocks(512LL * 384),  256>>>(Wq, D_EMB, wqs, D_EMB, 512, 1);    // 2
    split3_kernel<<<blocks(4096LL * 384), 256>>>(k,  D_EMB, ks,  D_EMB, 4096, 0);   // 3
    split3_kernel<<<blocks(512LL * 384),  256>>>(Wk, D_EMB, wks, D_EMB, 512, 1);    // 4
    rope_table_kernel<<<blocks(S_LEN * 64), 256>>>(rtab);                           // 5
    gemm_hmma<<<dim3(4, 32), 256, GEMM_SMEM>>>(qs, wqs, qh, 3 * D_EMB, D_AUG);      // 6 (profiled)
    gemm_hmma<<<dim3(4, 32), 256, GEMM_SMEM>>>(ks, wks, kh, 3 * D_EMB, D_AUG);      // 7
    split3_kernel<<<blocks(4096LL * 128), 256>>>(v + D_AUG, D_EMB, vs, D_AUG, 4096, 0);
    split3_kernel<<<blocks(512LL * 128),  256>>>(Wv, D_AUG, wvs, D_AUG, 512, 1);
    split3_kernel<<<blocks(1536LL * 128), 256>>>(Wo, D_EMB, wos, D_AUG, 1536, 1);
    gemm_hmma<<<dim3(4, 32), 256, GEMM_SMEM>>>(vs, wvs, vh, 3 * D_AUG, D_AUG);

    rope_split_kernel<<<blocks(8LL * S_LEN * 64), 256>>>(qh, kh, rtab,
                                                         pqhi, pqlo, pkhi, pklo);
    vt_split_kernel<<<dim3(64, 4, 8), dim3(32, 32)>>>(vh, pvthi, pvtlo);

    flash_hmma<<<dim3(16, 8), 256, FB_SMEM>>>(pqhi, pqlo, pkhi, pklo,
                                              pvthi, pvtlo, ats);

    gemm_hmma<<<dim3(12, 32), 256, GEMM_SMEM>>>(ats, wos, out, 3 * D_AUG, D_EMB);
}

// round 9
// speedup vs baseline: 3.2547x; 1.0324x over previous
#include <cuda_runtime.h>
#include <cuda_bf16.h>
#include <math.h>
#include <stdint.h>

#define BS_TOT 4096
#define S_LEN  2048
#define D_EMB  1536
#define D_AUG  512

// ---------------- device scratch ----------------
__device__ float g_qh[BS_TOT * D_AUG];
__device__ float g_kh[BS_TOT * D_AUG];
__device__ float g_vh[BS_TOT * D_AUG];
__device__ float g_rope[2 * S_LEN * 64];   // cos | sin

__device__ __align__(128) __nv_bfloat16 g_q_s   [BS_TOT * 3 * D_EMB];
__device__ __align__(128) __nv_bfloat16 g_k_s   [BS_TOT * 3 * D_EMB];
__device__ __align__(128) __nv_bfloat16 g_v_s   [BS_TOT * 3 * D_AUG];
__device__ __align__(128) __nv_bfloat16 g_attn_s[BS_TOT * 3 * D_AUG];
__device__ __align__(128) __nv_bfloat16 g_Wq_s  [D_AUG * 3 * D_EMB];
__device__ __align__(128) __nv_bfloat16 g_Wk_s  [D_AUG * 3 * D_EMB];
__device__ __align__(128) __nv_bfloat16 g_Wv_s  [D_AUG * 3 * D_AUG];
__device__ __align__(128) __nv_bfloat16 g_Wo_s  [D_EMB * 3 * D_AUG];

__device__ __align__(128) __nv_bfloat16 g_qhi[8 * S_LEN * 128];
__device__ __align__(128) __nv_bfloat16 g_qlo[8 * S_LEN * 128];
__device__ __align__(128) __nv_bfloat16 g_khi[8 * S_LEN * 128];
__device__ __align__(128) __nv_bfloat16 g_klo[8 * S_LEN * 128];
__device__ __align__(128) __nv_bfloat16 g_vthi[8 * 128 * S_LEN];
__device__ __align__(128) __nv_bfloat16 g_vtlo[8 * 128 * S_LEN];

extern __shared__ __align__(128) char dynsmem[];

// ---------------------------------------------------------------------------
__device__ __forceinline__ uint32_t smem_u32(const void* p) {
    uint32_t a;
    asm("{ .reg .u64 t; cvta.to.shared.u64 t, %1; cvt.u32.u64 %0, t; }" : "=r"(a) : "l"(p));
    return a;
}
__device__ __forceinline__ void cp16(uint32_t saddr, const void* gaddr) {
    asm volatile("cp.async.cg.shared.global [%0], [%1], 16;" :: "r"(saddr), "l"(gaddr) : "memory");
}
__device__ __forceinline__ void cp_commit() {
    asm volatile("cp.async.commit_group;" ::: "memory");
}
template <int N>
__device__ __forceinline__ void cp_wait() {
    asm volatile("cp.async.wait_group %0;" :: "n"(N) : "memory");
}
__device__ __forceinline__ void ldmx4(uint32_t* r, uint32_t addr) {
    asm volatile("ldmatrix.sync.aligned.m8n8.x4.shared.b16 {%0,%1,%2,%3}, [%4];"
                 : "=r"(r[0]), "=r"(r[1]), "=r"(r[2]), "=r"(r[3]) : "r"(addr));
}
__device__ __forceinline__ void mma_bf16(float* c, const uint32_t* a, uint32_t b0, uint32_t b1) {
    asm volatile(
        "mma.sync.aligned.m16n8k16.row.col.f32.bf16.bf16.f32 "
        "{%0,%1,%2,%3}, {%4,%5,%6,%7}, {%8,%9}, {%0,%1,%2,%3};"
        : "+f"(c[0]), "+f"(c[1]), "+f"(c[2]), "+f"(c[3])
        : "r"(a[0]), "r"(a[1]), "r"(a[2]), "r"(a[3]), "r"(b0), "r"(b1));
}
__device__ __forceinline__ float ex2(float x) {
    float y; asm("ex2.approx.f32 %0, %1;" : "=f"(y) : "f"(x)); return y;
}

// ---------------------------------------------------------------------------
// split helpers
// ---------------------------------------------------------------------------
__device__ __forceinline__ void split3_row(const float* srow, __nv_bfloat16* drow,
                                           int K, int c4, int bmode)
{
    float4 x = *(const float4*)(srow + c4);
    float xs[4] = {x.x, x.y, x.z, x.w};
    __nv_bfloat162 h0, h1, l0, l1;
    __nv_bfloat16 h[4], l[4];
#pragma unroll
    for (int j = 0; j < 4; j++) {
        h[j] = __float2bfloat16(xs[j]);
        l[j] = __float2bfloat16(xs[j] - __bfloat162float(h[j]));
    }
    h0.x = h[0]; h0.y = h[1]; h1.x = h[2]; h1.y = h[3];
    l0.x = l[0]; l0.y = l[1]; l1.x = l[2]; l1.y = l[3];
    __nv_bfloat16* d = drow + c4;
    *(__nv_bfloat162*)(d)     = h0;  *(__nv_bfloat162*)(d + 2)     = h1;
    if (bmode == 0) {
        *(__nv_bfloat162*)(d + K)     = h0;  *(__nv_bfloat162*)(d + K + 2)     = h1;
        *(__nv_bfloat162*)(d + 2 * K) = l0;  *(__nv_bfloat162*)(d + 2 * K + 2) = l1;
    } else {
        *(__nv_bfloat162*)(d + K)     = l0;  *(__nv_bfloat162*)(d + K + 2)     = l1;
        *(__nv_bfloat162*)(d + 2 * K) = h0;  *(__nv_bfloat162*)(d + 2 * K + 2) = h1;
    }
}

__global__ void split_qk_kernel(const float* __restrict__ q, const float* __restrict__ k,
                                __nv_bfloat16* __restrict__ qs, __nv_bfloat16* __restrict__ ks)
{
    int i = blockIdx.x * blockDim.x + threadIdx.x;       // 8192*384
    int rt = i / 384, c4 = (i - rt * 384) << 2;
    const float* src = (rt < 4096) ? q : k;
    __nv_bfloat16* dst = (rt < 4096) ? qs : ks;
    int r = rt & 4095;
    split3_row(src + (size_t)r * D_EMB, dst + (size_t)r * 3 * D_EMB, D_EMB, c4, 0);
}

__global__ void split_wqk_kernel(const float* __restrict__ Wq, const float* __restrict__ Wk,
                                 __nv_bfloat16* __restrict__ wqs, __nv_bfloat16* __restrict__ wks)
{
    int i = blockIdx.x * blockDim.x + threadIdx.x;       // 1024*384
    int rt = i / 384, c4 = (i - rt * 384) << 2;
    const float* src = (rt < 512) ? Wq : Wk;
    __nv_bfloat16* dst = (rt < 512) ? wqs : wks;
    int r = rt & 511;
    split3_row(src + (size_t)r * D_EMB, dst + (size_t)r * 3 * D_EMB, D_EMB, c4, 1);
}

// v (rows 4096, stride D_EMB, offset D_AUG), Wv (512, stride D_AUG),
// Wo (1536 rows, STRIDE D_EMB — W_o is 1536x1536, we take cols [0,512)).
__global__ void split_vwo_kernel(const float* __restrict__ v, const float* __restrict__ Wv,
                                 const float* __restrict__ Wo,
                                 __nv_bfloat16* __restrict__ vs, __nv_bfloat16* __restrict__ wvs,
                                 __nv_bfloat16* __restrict__ wos)
{
    int i = blockIdx.x * blockDim.x + threadIdx.x;       // 6144*128
    int rt = i >> 7, c4 = (i & 127) << 2;
    if (rt < 4096) {
        split3_row(v + (size_t)rt * D_EMB + D_AUG, vs + (size_t)rt * 3 * D_AUG, D_AUG, c4, 0);
    } else if (rt < 4608) {
        int r = rt - 4096;
        split3_row(Wv + (size_t)r * D_AUG, wvs + (size_t)r * 3 * D_AUG, D_AUG, c4, 1);
    } else {
        int r = rt - 4608;
        // FIX (R8 bug): Wo row stride is D_EMB, not D_AUG.
        split3_row(Wo + (size_t)r * D_EMB, wos + (size_t)r * 3 * D_AUG, D_AUG, c4, 1);
    }
}

// ---------------------------------------------------------------------------
// HMMA GEMM: C[M,N] = A[M,K3] @ B[N,K3]^T  (occupancy 2)
// ---------------------------------------------------------------------------
#define BM 128
#define BN 128
#define BK 32
#define LDSM 40
#define STAGES 3
#define TSTG (BM * LDSM)
#define GEMM_SMEM (2 * STAGES * TSTG * 2)

__global__ void __launch_bounds__(256, 2)
gemm_hmma(const __nv_bfloat16* __restrict__ A, const __nv_bfloat16* __restrict__ B,
          float* __restrict__ C, int K3, int ldc)
{
    __nv_bfloat16* As = (__nv_bfloat16*)dynsmem;
    __nv_bfloat16* Bs = As + STAGES * TSTG;

    const int tid  = threadIdx.x;
    const int wid  = tid >> 5, lane = tid & 31;
    const int m0   = blockIdx.y * BM, n0 = blockIdx.x * BN;
    const int wm   = (wid >> 2) * 64;
    const int wn   = (wid & 3) * 32;

    const int lrow0 = tid >> 2,         lq0 = tid & 3;
    const int lrow1 = (tid + 256) >> 2, lq1 = (tid + 256) & 3;

    const __nv_bfloat16* Ag0 = A + (size_t)(m0 + lrow0) * K3 + lq0 * 8;
    const __nv_bfloat16* Ag1 = A + (size_t)(m0 + lrow1) * K3 + lq1 * 8;
    const __nv_bfloat16* Bg0 = B + (size_t)(n0 + lrow0) * K3 + lq0 * 8;
    const __nv_bfloat16* Bg1 = B + (size_t)(n0 + lrow1) * K3 + lq1 * 8;
    const uint32_t sA0 = smem_u32(As) + (lrow0 * LDSM + lq0 * 8) * 2;
    const uint32_t sA1 = smem_u32(As) + (lrow1 * LDSM + lq1 * 8) * 2;
    const uint32_t sB0 = smem_u32(Bs) + (lrow0 * LDSM + lq0 * 8) * 2;
    const uint32_t sB1 = smem_u32(Bs) + (lrow1 * LDSM + lq1 * 8) * 2;

    const int KT = K3 / BK;

    float acc[4][4][4];
#pragma unroll
    for (int i = 0; i < 4; i++)
#pragma unroll
        for (int j = 0; j < 4; j++)
#pragma unroll
            for (int t = 0; t < 4; t++) acc[i][j][t] = 0.f;

    const uint32_t als = smem_u32(As) + ((wm + (lane & 15)) * LDSM + (lane >> 4) * 8) * 2;
    const uint32_t bls = smem_u32(Bs) + ((wn + (lane & 15)) * LDSM + (lane >> 4) * 8) * 2;

#pragma unroll
    for (int s = 0; s < STAGES - 1; s++) {
        int k0 = s * BK;
        cp16(sA0 + s * TSTG * 2, Ag0 + k0);
        cp16(sA1 + s * TSTG * 2, Ag1 + k0);
        cp16(sB0 + s * TSTG * 2, Bg0 + k0);
        cp16(sB1 + s * TSTG * 2, Bg1 + k0);
        cp_commit();
    }

    for (int it = 0; it < KT; it++) {
        cp_wait<STAGES - 2>();
        __syncthreads();
        const int sc = it % STAGES;
        const uint32_t abase = als + sc * TSTG * 2;
        const uint32_t bbase = bls + sc * TSTG * 2;
#pragma unroll
        for (int ks = 0; ks < 2; ks++) {
            uint32_t af[4][4], bf[2][4];
#pragma unroll
            for (int mt = 0; mt < 4; mt++)
                ldmx4(af[mt], abase + (mt * 16 * LDSM + ks * 16) * 2);
#pragma unroll
            for (int nt2 = 0; nt2 < 2; nt2++)
                ldmx4(bf[nt2], bbase + (nt2 * 16 * LDSM + ks * 16) * 2);
#pragma unroll
            for (int mt = 0; mt < 4; mt++)
#pragma unroll
                for (int nt = 0; nt < 4; nt++)
                    mma_bf16(acc[mt][nt], af[mt],
                             bf[nt >> 1][nt & 1], bf[nt >> 1][(nt & 1) + 2]);
        }
        const int nxt = it + STAGES - 1;
        if (nxt < KT) {
            const int sn = nxt % STAGES;
            const int k0 = nxt * BK;
            cp16(sA0 + sn * TSTG * 2, Ag0 + k0);
            cp16(sA1 + sn * TSTG * 2, Ag1 + k0);
            cp16(sB0 + sn * TSTG * 2, Bg0 + k0);
            cp16(sB1 + sn * TSTG * 2, Bg1 + k0);
        }
        cp_commit();
    }

    const int rbase = m0 + wm + (lane >> 2);
    const int cbase = n0 + wn + (lane & 3) * 2;
#pragma unroll
    for (int mt = 0; mt < 4; mt++) {
#pragma unroll
        for (int nt = 0; nt < 4; nt++) {
            float* p0 = C + (size_t)(rbase + mt * 16) * ldc + cbase + nt * 8;
            float* p1 = p0 + 8 * ldc;
            *(float2*)p0 = make_float2(acc[mt][nt][0], acc[mt][nt][1]);
            *(float2*)p1 = make_float2(acc[mt][nt][2], acc[mt][nt][3]);
        }
    }
}

// ---------------------------------------------------------------------------
// RoPE table
// ---------------------------------------------------------------------------
__global__ void rope_table_kernel(float* __restrict__ tab)
{
    int idx = blockIdx.x * blockDim.x + threadIdx.x;   // 2048*64
    if (idx >= S_LEN * 64) return;
    int pair = idx & 63, s = idx >> 6;
    float freq = (float)exp(-(double)(2 * pair) * (1.0 / 128.0) * 9.210340371976184);
    float ang  = (float)s * freq;
    tab[idx]              = cosf(ang);
    tab[S_LEN * 64 + idx] = sinf(ang);
}

// ---------------------------------------------------------------------------
// RoPE + split-bf16 plane emission
// ---------------------------------------------------------------------------
__global__ void rope_split_kernel(const float* __restrict__ qh, const float* __restrict__ kh,
                                  const float* __restrict__ tab,
                                  __nv_bfloat16* __restrict__ qhi, __nv_bfloat16* __restrict__ qlo,
                                  __nv_bfloat16* __restrict__ khi, __nv_bfloat16* __restrict__ klo)
{
    int idx  = blockIdx.x * blockDim.x + threadIdx.x;  // 8*2048*64
    int pair = idx & 63;
    int s    = (idx >> 6) & (S_LEN - 1);
    int bh   = idx >> 17;
    int b = bh >> 2, h = bh & 3;

    float c  = tab[s * 64 + pair];
    float sn = tab[S_LEN * 64 + s * 64 + pair];

    size_t src = (size_t)(b * S_LEN + s) * D_AUG + h * 128 + 2 * pair;
    size_t dst = (size_t)bh * S_LEN * 128 + (size_t)s * 128 + 2 * pair;
    const float qscale = 0.08838834764831845f;

    float q1 = qh[src], q2 = qh[src + 1];
    float qa = (q1 * c - q2 * sn) * qscale;
    float qb = (q1 * sn + q2 * c) * qscale;
    __nv_bfloat16 ha = __float2bfloat16(qa), hb = __float2bfloat16(qb);
    __nv_bfloat162 hv; hv.x = ha; hv.y = hb;
    __nv_bfloat162 lv;
    lv.x = __float2bfloat16(qa - __bfloat162float(ha));
    lv.y = __float2bfloat16(qb - __bfloat162float(hb));
    *(__nv_bfloat162*)(qhi + dst) = hv;
    *(__nv_bfloat162*)(qlo + dst) = lv;

    float k1 = kh[src], k2 = kh[src + 1];
    float ka = k1 * c - k2 * sn;
    float kb = k1 * sn + k2 * c;
    ha = __float2bfloat16(ka); hb = __float2bfloat16(kb);
    hv.x = ha; hv.y = hb;
    lv.x = __float2bfloat16(ka - __bfloat162float(ha));
    lv.y = __float2bfloat16(kb - __bfloat162float(hb));
    *(__nv_bfloat162*)(khi + dst) = hv;
    *(__nv_bfloat162*)(klo + dst) = lv;
}

// ---------------------------------------------------------------------------
// V transpose + split
// ---------------------------------------------------------------------------
__global__ void vt_split_kernel(const float* __restrict__ vh,
                                __nv_bfloat16* __restrict__ vthi, __nv_bfloat16* __restrict__ vtlo)
{
    __shared__ float tile[32][33];
    int bh = blockIdx.z, b = bh >> 2, h = bh & 3;
    int tx = threadIdx.x, ty = threadIdx.y;
    int s_in = blockIdx.x * 32 + ty;
    int d_in = blockIdx.y * 32 + tx;
    tile[ty][tx] = vh[(size_t)(b * S_LEN + s_in) * D_AUG + h * 128 + d_in];
    __syncthreads();
    int d_out = blockIdx.y * 32 + ty;
    int s_out = blockIdx.x * 32 + tx;
    float v = tile[tx][ty];
    __nv_bfloat16 hi = __float2bfloat16(v);
    size_t dst = (size_t)bh * 128 * S_LEN + (size_t)d_out * S_LEN + s_out;
    vthi[dst] = hi;
    vtlo[dst] = __float2bfloat16(v - __bfloat162float(hi));
}

// ---------------------------------------------------------------------------
// HMMA flash attention
// ---------------------------------------------------------------------------
#define FB_QHI 0
#define FB_QLO 17408
#define FB_KHI 34816
#define FB_KLO 52224
#define FB_VHI 69632
#define FB_VLO 88064
#define FB_PHI 106496
#define FB_PLO 115712
#define FB_RED 124928
#define FB_SMEM 125952
#define L2E 1.4426950408889634f

__global__ void __launch_bounds__(256, 1)
flash_hmma(const __nv_bfloat16* __restrict__ qhi, const __nv_bfloat16* __restrict__ qlo,
           const __nv_bfloat16* __restrict__ khi, const __nv_bfloat16* __restrict__ klo,
           const __nv_bfloat16* __restrict__ vthi, const __nv_bfloat16* __restrict__ vtlo,
           __nv_bfloat16* __restrict__ attn_s)
{
    char* fsm = dynsmem;
    const uint32_t sb = smem_u32(fsm);
    float* red = (float*)(fsm + FB_RED);

    const int tid  = threadIdx.x;
    const int lane = tid & 31;
    const int wid  = tid >> 5;
    const int mw   = wid >> 1;
    const int nw   = wid & 1;
    const int bh   = blockIdx.y;
    const int b    = bh >> 2, hh = bh & 3;

    const size_t qkplane = (size_t)bh * S_LEN * 128;
    const size_t vplane  = (size_t)bh * 128 * S_LEN;

    const uint32_t aoffQ = (mw * 16 + (lane & 15)) * 272 + (lane >> 4) * 16;
    const uint32_t boffK = (nw * 32 + (lane & 15)) * 272 + (lane >> 4) * 16;
    const uint32_t aoffP = (mw * 16 + (lane & 15)) * 144 + (lane >> 4) * 16;
    const uint32_t boffV = (nw * 64 + (lane & 15)) * 144 + (lane >> 4) * 16;

    const int r0 = lane >> 2;
    const int c2 = (lane & 3) * 2;
    const int rloc0 = mw * 16 + r0;
    const int rloc1 = rloc0 + 8;

    for (int qq = 0; qq < 2; qq++) {
        const int qb = qq ? 31 - (int)blockIdx.x : (int)blockIdx.x;

        __syncthreads();
        {
            const __nv_bfloat16* srcs[2] = {qhi + qkplane + (size_t)qb * 64 * 128,
                                            qlo + qkplane + (size_t)qb * 64 * 128};
#pragma unroll
            for (int p = 0; p < 2; p++)
#pragma unroll
                for (int i = 0; i < 4; i++) {
                    int c = tid + i * 256;
                    int r = c >> 4, qx = c & 15;
                    cp16(sb + FB_QHI + p * 17408 + r * 272 + qx * 16,
                         srcs[p] + (size_t)r * 128 + qx * 8);
                }
            cp_commit();
        }
        cp_wait<0>();
        __syncthreads();

        float m0 = -1e30f, m1 = -1e30f, l0 = 0.f, l1 = 0.f;
        float o[8][4];
#pragma unroll
        for (int f = 0; f < 8; f++)
#pragma unroll
            for (int e = 0; e < 4; e++) o[f][e] = 0.f;

        for (int jb = 0; jb <= qb; jb++) {
            __syncthreads();
            {
                const __nv_bfloat16* ks[2] = {khi + qkplane + (size_t)jb * 64 * 128,
                                              klo + qkplane + (size_t)jb * 64 * 128};
#pragma unroll
                for (int p = 0; p < 2; p++)
#pragma unroll
                    for (int i = 0; i < 4; i++) {
                        int c = tid + i * 256;
                        int r = c >> 4, qx = c & 15;
                        cp16(sb + FB_KHI + p * 17408 + r * 272 + qx * 16,
                             ks[p] + (size_t)r * 128 + qx * 8);
                    }
                const __nv_bfloat16* vs[2] = {vthi + vplane + jb * 64,
                                              vtlo + vplane + jb * 64};
#pragma unroll
                for (int p = 0; p < 2; p++)
#pragma unroll
                    for (int i = 0; i < 4; i++) {
                        int c = tid + i * 256;
                        int r = c >> 3, qx = c & 7;
                        cp16(sb + FB_VHI + p * 18432 + r * 144 + qx * 16,
                             vs[p] + (size_t)r * S_LEN + qx * 8);
                    }
                cp_commit();
            }
            cp_wait<0>();
            __syncthreads();

            float sacc[4][4];
#pragma unroll
            for (int f = 0; f < 4; f++)
#pragma unroll
                for (int e = 0; e < 4; e++) sacc[f][e] = 0.f;

            const uint32_t aB[3] = {sb + FB_QHI, sb + FB_QHI, sb + FB_QLO};
            const uint32_t bB[3] = {sb + FB_KHI, sb + FB_KLO, sb + FB_KHI};
#pragma unroll
            for (int ps = 0; ps < 3; ps++) {
                const uint32_t ab = aB[ps] + aoffQ;
                const uint32_t bb0 = bB[ps] + boffK;
                const uint32_t bb1 = bb0 + 16 * 272;
#pragma unroll
                for (int ks = 0; ks < 8; ks++) {
                    uint32_t a[4], q0[4], q1[4];
                    ldmx4(a,  ab  + ks * 32);
                    ldmx4(q0, bb0 + ks * 32);
                    ldmx4(q1, bb1 + ks * 32);
                    mma_bf16(sacc[0], a, q0[0], q0[2]);
                    mma_bf16(sacc[1], a, q0[1], q0[3]);
                    mma_bf16(sacc[2], a, q1[0], q1[2]);
                    mma_bf16(sacc[3], a, q1[1], q1[3]);
                }
            }

            if (jb == qb) {
#pragma unroll
                for (int f = 0; f < 4; f++) {
                    int colb = nw * 32 + (f >> 1) * 16 + (f & 1) * 8 + c2;
#pragma unroll
                    for (int e = 0; e < 4; e++) {
                        int row = mw * 16 + r0 + ((e >> 1) << 3);
                        int col = colb + (e & 1);
                        if (col > row) sacc[f][e] = -1e30f;
                    }
                }
            }

            float pm0 = -1e30f, pm1 = -1e30f;
#pragma unroll
            for (int f = 0; f < 4; f++) {
                pm0 = fmaxf(pm0, fmaxf(sacc[f][0], sacc[f][1]));
                pm1 = fmaxf(pm1, fmaxf(sacc[f][2], sacc[f][3]));
            }
            pm0 = fmaxf(pm0, __shfl_xor_sync(0xffffffffu, pm0, 1));
            pm0 = fmaxf(pm0, __shfl_xor_sync(0xffffffffu, pm0, 2));
            pm1 = fmaxf(pm1, __shfl_xor_sync(0xffffffffu, pm1, 1));
            pm1 = fmaxf(pm1, __shfl_xor_sync(0xffffffffu, pm1, 2));
            if ((lane & 3) == 0) {
                red[nw * 64 + rloc0] = pm0;
                red[nw * 64 + rloc1] = pm1;
            }
            __syncthreads();
            float rm0 = fmaxf(red[rloc0], red[64 + rloc0]);
            float rm1 = fmaxf(red[rloc1], red[64 + rloc1]);
            float mn0 = fmaxf(m0, rm0), mn1 = fmaxf(m1, rm1);
            float scl0 = ex2((m0 - mn0) * L2E);
            float scl1 = ex2((m1 - mn1) * L2E);

            float ts0 = 0.f, ts1 = 0.f;
#pragma unroll
            for (int f = 0; f < 4; f++) {
                int col = nw * 32 + (f >> 1) * 16 + (f & 1) * 8 + c2;
                float p00 = ex2((sacc[f][0] - mn0) * L2E);
                float p01 = ex2((sacc[f][1] - mn0) * L2E);
                float p10 = ex2((sacc[f][2] - mn1) * L2E);
                float p11 = ex2((sacc[f][3] - mn1) * L2E);
                ts0 += p00 + p01;
                ts1 += p10 + p11;
                __nv_bfloat16 h00 = __float2bfloat16(p00), h01 = __float2bfloat16(p01);
                __nv_bfloat16 h10 = __float2bfloat16(p10), h11 = __float2bfloat16(p11);
                __nv_bfloat162 hv, lv;
                hv.x = h00; hv.y = h01;
                lv.x = __float2bfloat16(p00 - __bfloat162float(h00));
                lv.y = __float2bfloat16(p01 - __bfloat162float(h01));
                *(__nv_bfloat162*)(fsm + FB_PHI + rloc0 * 144 + col * 2) = hv;
                *(__nv_bfloat162*)(fsm + FB_PLO + rloc0 * 144 + col * 2) = lv;
                hv.x = h10; hv.y = h11;
                lv.x = __float2bfloat16(p10 - __bfloat162float(h10));
                lv.y = __float2bfloat16(p11 - __bfloat162float(h11));
                *(__nv_bfloat162*)(fsm + FB_PHI + rloc1 * 144 + col * 2) = hv;
                *(__nv_bfloat162*)(fsm + FB_PLO + rloc1 * 144 + col * 2) = lv;
            }
            ts0 += __shfl_xor_sync(0xffffffffu, ts0, 1);
            ts0 += __shfl_xor_sync(0xffffffffu, ts0, 2);
            ts1 += __shfl_xor_sync(0xffffffffu, ts1, 1);
            ts1 += __shfl_xor_sync(0xffffffffu, ts1, 2);
            if ((lane & 3) == 0) {
                red[128 + nw * 64 + rloc0] = ts0;
                red[128 + nw * 64 + rloc1] = ts1;
            }
            __syncthreads();
            l0 = l0 * scl0 + red[128 + rloc0] + red[128 + 64 + rloc0];
            l1 = l1 * scl1 + red[128 + rloc1] + red[128 + 64 + rloc1];
            m0 = mn0; m1 = mn1;
#pragma unroll
            for (int f = 0; f < 8; f++) {
                o[f][0] *= scl0; o[f][1] *= scl0;
                o[f][2] *= scl1; o[f][3] *= scl1;
            }

            const uint32_t aP[3] = {sb + FB_PHI, sb + FB_PHI, sb + FB_PLO};
            const uint32_t bV[3] = {sb + FB_VHI, sb + FB_VLO, sb + FB_VHI};
#pragma unroll
            for (int ps = 0; ps < 3; ps++) {
                const uint32_t ab = aP[ps] + aoffP;
                const uint32_t bb = bV[ps] + boffV;
#pragma unroll
                for (int ks = 0; ks < 4; ks++) {
                    uint32_t a[4];
                    ldmx4(a, ab + ks * 32);
#pragma unroll
                    for (int g2 = 0; g2 < 4; g2++) {
                        uint32_t qv[4];
                        ldmx4(qv, bb + g2 * (16 * 144) + ks * 32);
                        mma_bf16(o[g2 * 2 + 0], a, qv[0], qv[2]);
                        mma_bf16(o[g2 * 2 + 1], a, qv[1], qv[3]);
                    }
                }
            }
        }

        float inv0 = 1.0f / l0, inv1 = 1.0f / l1;
        size_t rg0 = (size_t)(b * S_LEN + qb * 64 + rloc0) * (3 * D_AUG);
        size_t rg1 = (size_t)(b * S_LEN + qb * 64 + rloc1) * (3 * D_AUG);
#pragma unroll
        for (int f = 0; f < 8; f++) {
            int col = hh * 128 + nw * 64 + (f >> 1) * 16 + (f & 1) * 8 + c2;
            float v0 = o[f][0] * inv0, v1 = o[f][1] * inv0;
            __nv_bfloat16 h0 = __float2bfloat16(v0), h1 = __float2bfloat16(v1);
            __nv_bfloat162 hv, lv;
            hv.x = h0; hv.y = h1;
            lv.x = __float2bfloat16(v0 - __bfloat162float(h0));
            lv.y = __float2bfloat16(v1 - __bfloat162float(h1));
            *(__nv_bfloat162*)(attn_s + rg0 + col)             = hv;
            *(__nv_bfloat162*)(attn_s + rg0 + col + D_AUG)     = hv;
            *(__nv_bfloat162*)(attn_s + rg0 + col + 2 * D_AUG) = lv;
            v0 = o[f][2] * inv1; v1 = o[f][3] * inv1;
            h0 = __float2bfloat16(v0); h1 = __float2bfloat16(v1);
            hv.x = h0; hv.y = h1;
            lv.x = __float2bfloat16(v0 - __bfloat162float(h0));
            lv.y = __float2bfloat16(v1 - __bfloat162float(h1));
            *(__nv_bfloat162*)(attn_s + rg1 + col)             = hv;
            *(__nv_bfloat162*)(attn_s + rg1 + col + D_AUG)     = hv;
            *(__nv_bfloat162*)(attn_s + rg1 + col + 2 * D_AUG) = lv;
        }
    }
}

// ---------------------------------------------------------------------------
extern "C" void kernel_launch(void* const* d_in, const int* in_sizes, int n_in,
                              void* d_out, int out_size)
{
    const float* q  = (const float*)d_in[0];
    const float* k  = (const float*)d_in[1];
    const float* v  = (const float*)d_in[2];
    const float* Wq = (const float*)d_in[3];
    const float* Wk = (const float*)d_in[4];
    const float* Wv = (const float*)d_in[5];
    const float* Wo = (const float*)d_in[6];
    float* out = (float*)d_out;

    float *qh, *kh, *vh, *rtab;
    cudaGetSymbolAddress((void**)&qh,   g_qh);
    cudaGetSymbolAddress((void**)&kh,   g_kh);
    cudaGetSymbolAddress((void**)&vh,   g_vh);
    cudaGetSymbolAddress((void**)&rtab, g_rope);
    __nv_bfloat16 *qs, *ks, *vs, *ats, *wqs, *wks, *wvs, *wos;
    __nv_bfloat16 *pqhi, *pqlo, *pkhi, *pklo, *pvthi, *pvtlo;
    cudaGetSymbolAddress((void**)&qs,  g_q_s);
    cudaGetSymbolAddress((void**)&ks,  g_k_s);
    cudaGetSymbolAddress((void**)&vs,  g_v_s);
    cudaGetSymbolAddress((void**)&ats, g_attn_s);
    cudaGetSymbolAddress((void**)&wqs, g_Wq_s);
    cudaGetSymbolAddress((void**)&wks, g_Wk_s);
    cudaGetSymbolAddress((void**)&wvs, g_Wv_s);
    cudaGetSymbolAddress((void**)&wos, g_Wo_s);
    cudaGetSymbolAddress((void**)&pqhi, g_qhi);
    cudaGetSymbolAddress((void**)&pqlo, g_qlo);
    cudaGetSymbolAddress((void**)&pkhi, g_khi);
    cudaGetSymbolAddress((void**)&pklo, g_klo);
    cudaGetSymbolAddress((void**)&pvthi, g_vthi);
    cudaGetSymbolAddress((void**)&pvtlo, g_vtlo);

    cudaFuncSetAttribute(gemm_hmma,  cudaFuncAttributeMaxDynamicSharedMemorySize, GEMM_SMEM);
    cudaFuncSetAttribute(flash_hmma, cudaFuncAttributeMaxDynamicSharedMemorySize, FB_SMEM);

    // #1 q+k split
    split_qk_kernel<<<12288, 256>>>(q, k, qs, ks);
    // #2 Wq+Wk split
    split_wqk_kernel<<<1536, 256>>>(Wq, Wk, wqs, wks);
    // #3 rope table
    rope_table_kernel<<<512, 256>>>(rtab);
    // #4 q projection (PROFILED launch)
    gemm_hmma<<<dim3(4, 32), 256, GEMM_SMEM>>>(qs, wqs, qh, 3 * D_EMB, D_AUG);
    // #5 k projection
    gemm_hmma<<<dim3(4, 32), 256, GEMM_SMEM>>>(ks, wks, kh, 3 * D_EMB, D_AUG);
    // #6 v + Wv + Wo split
    split_vwo_kernel<<<3072, 256>>>(v, Wv, Wo, vs, wvs, wos);
    // #7 v projection
    gemm_hmma<<<dim3(4, 32), 256, GEMM_SMEM>>>(vs, wvs, vh, 3 * D_AUG, D_AUG);
    // #8 rope + plane split
    rope_split_kernel<<<4096, 256>>>(qh, kh, rtab, pqhi, pqlo, pkhi, pklo);
    // #9 V transpose + split
    vt_split_kernel<<<dim3(64, 4, 8), dim3(32, 32)>>>(vh, pvthi, pvtlo);
    // #10 flash attention
    flash_hmma<<<dim3(16, 8), 256, FB_SMEM>>>(pqhi, pqlo, pkhi, pklo, pvthi, pvtlo, ats);
    // #11 output projection
    gemm_hmma<<<dim3(12, 32), 256, GEMM_SMEM>>>(ats, wos, out, 3 * D_AUG, D_EMB);
}

// round 10
// speedup vs baseline: 3.5004x; 1.0755x over previous
#include <cuda_runtime.h>
#include <cuda_bf16.h>
#include <math.h>
#include <stdint.h>

#define BS_TOT 4096
#define S_LEN  2048
#define D_EMB  1536
#define D_AUG  512

// ---------------- device scratch ----------------
__device__ float g_qh[BS_TOT * D_AUG];
__device__ float g_kh[BS_TOT * D_AUG];
__device__ float g_vh[BS_TOT * D_AUG];
__device__ float g_rope[2 * S_LEN * 64];   // cos | sin

__device__ __align__(128) __nv_bfloat16 g_q_s   [BS_TOT * 3 * D_EMB];
__device__ __align__(128) __nv_bfloat16 g_k_s   [BS_TOT * 3 * D_EMB];
__device__ __align__(128) __nv_bfloat16 g_v_s   [BS_TOT * 3 * D_AUG];
__device__ __align__(128) __nv_bfloat16 g_attn_s[BS_TOT * 3 * D_AUG];
__device__ __align__(128) __nv_bfloat16 g_Wq_s  [D_AUG * 3 * D_EMB];
__device__ __align__(128) __nv_bfloat16 g_Wk_s  [D_AUG * 3 * D_EMB];
__device__ __align__(128) __nv_bfloat16 g_Wv_s  [D_AUG * 3 * D_AUG];
__device__ __align__(128) __nv_bfloat16 g_Wo_s  [D_EMB * 3 * D_AUG];

__device__ __align__(128) __nv_bfloat16 g_qhi[8 * S_LEN * 128];
__device__ __align__(128) __nv_bfloat16 g_qlo[8 * S_LEN * 128];
__device__ __align__(128) __nv_bfloat16 g_khi[8 * S_LEN * 128];
__device__ __align__(128) __nv_bfloat16 g_klo[8 * S_LEN * 128];
__device__ __align__(128) __nv_bfloat16 g_vthi[8 * 128 * S_LEN];
__device__ __align__(128) __nv_bfloat16 g_vtlo[8 * 128 * S_LEN];

extern __shared__ __align__(128) char dynsmem[];

// ---------------------------------------------------------------------------
__device__ __forceinline__ uint32_t smem_u32(const void* p) {
    uint32_t a;
    asm("{ .reg .u64 t; cvta.to.shared.u64 t, %1; cvt.u32.u64 %0, t; }" : "=r"(a) : "l"(p));
    return a;
}
__device__ __forceinline__ void cp16(uint32_t saddr, const void* gaddr) {
    asm volatile("cp.async.cg.shared.global [%0], [%1], 16;" :: "r"(saddr), "l"(gaddr) : "memory");
}
__device__ __forceinline__ void cp_commit() {
    asm volatile("cp.async.commit_group;" ::: "memory");
}
template <int N>
__device__ __forceinline__ void cp_wait() {
    asm volatile("cp.async.wait_group %0;" :: "n"(N) : "memory");
}
__device__ __forceinline__ void ldmx4(uint32_t* r, uint32_t addr) {
    asm volatile("ldmatrix.sync.aligned.m8n8.x4.shared.b16 {%0,%1,%2,%3}, [%4];"
                 : "=r"(r[0]), "=r"(r[1]), "=r"(r[2]), "=r"(r[3]) : "r"(addr));
}
__device__ __forceinline__ void mma_bf16(float* c, const uint32_t* a, uint32_t b0, uint32_t b1) {
    asm volatile(
        "mma.sync.aligned.m16n8k16.row.col.f32.bf16.bf16.f32 "
        "{%0,%1,%2,%3}, {%4,%5,%6,%7}, {%8,%9}, {%0,%1,%2,%3};"
        : "+f"(c[0]), "+f"(c[1]), "+f"(c[2]), "+f"(c[3])
        : "r"(a[0]), "r"(a[1]), "r"(a[2]), "r"(a[3]), "r"(b0), "r"(b1));
}
__device__ __forceinline__ float ex2(float x) {
    float y; asm("ex2.approx.f32 %0, %1;" : "=f"(y) : "f"(x)); return y;
}

// ---------------------------------------------------------------------------
// split helpers
// ---------------------------------------------------------------------------
__device__ __forceinline__ void split3_row(const float* srow, __nv_bfloat16* drow,
                                           int K, int c4, int bmode)
{
    float4 x = *(const float4*)(srow + c4);
    float xs[4] = {x.x, x.y, x.z, x.w};
    __nv_bfloat162 h0, h1, l0, l1;
    __nv_bfloat16 h[4], l[4];
#pragma unroll
    for (int j = 0; j < 4; j++) {
        h[j] = __float2bfloat16(xs[j]);
        l[j] = __float2bfloat16(xs[j] - __bfloat162float(h[j]));
    }
    h0.x = h[0]; h0.y = h[1]; h1.x = h[2]; h1.y = h[3];
    l0.x = l[0]; l0.y = l[1]; l1.x = l[2]; l1.y = l[3];
    __nv_bfloat16* d = drow + c4;
    *(__nv_bfloat162*)(d)     = h0;  *(__nv_bfloat162*)(d + 2)     = h1;
    if (bmode == 0) {
        *(__nv_bfloat162*)(d + K)     = h0;  *(__nv_bfloat162*)(d + K + 2)     = h1;
        *(__nv_bfloat162*)(d + 2 * K) = l0;  *(__nv_bfloat162*)(d + 2 * K + 2) = l1;
    } else {
        *(__nv_bfloat162*)(d + K)     = l0;  *(__nv_bfloat162*)(d + K + 2)     = l1;
        *(__nv_bfloat162*)(d + 2 * K) = h0;  *(__nv_bfloat162*)(d + 2 * K + 2) = h1;
    }
}

__global__ void split_qk_kernel(const float* __restrict__ q, const float* __restrict__ k,
                                __nv_bfloat16* __restrict__ qs, __nv_bfloat16* __restrict__ ks)
{
    int i = blockIdx.x * blockDim.x + threadIdx.x;       // 8192*384
    int rt = i / 384, c4 = (i - rt * 384) << 2;
    const float* src = (rt < 4096) ? q : k;
    __nv_bfloat16* dst = (rt < 4096) ? qs : ks;
    int r = rt & 4095;
    split3_row(src + (size_t)r * D_EMB, dst + (size_t)r * 3 * D_EMB, D_EMB, c4, 0);
}

__global__ void split_wqk_kernel(const float* __restrict__ Wq, const float* __restrict__ Wk,
                                 __nv_bfloat16* __restrict__ wqs, __nv_bfloat16* __restrict__ wks)
{
    int i = blockIdx.x * blockDim.x + threadIdx.x;       // 1024*384
    int rt = i / 384, c4 = (i - rt * 384) << 2;
    const float* src = (rt < 512) ? Wq : Wk;
    __nv_bfloat16* dst = (rt < 512) ? wqs : wks;
    int r = rt & 511;
    split3_row(src + (size_t)r * D_EMB, dst + (size_t)r * 3 * D_EMB, D_EMB, c4, 1);
}

// v (rows 4096, stride D_EMB, offset D_AUG), Wv (512, stride D_AUG),
// Wo (1536 rows, STRIDE D_EMB — W_o is 1536x1536, cols [0,512)).
__global__ void split_vwo_kernel(const float* __restrict__ v, const float* __restrict__ Wv,
                                 const float* __restrict__ Wo,
                                 __nv_bfloat16* __restrict__ vs, __nv_bfloat16* __restrict__ wvs,
                                 __nv_bfloat16* __restrict__ wos)
{
    int i = blockIdx.x * blockDim.x + threadIdx.x;       // 6144*128
    int rt = i >> 7, c4 = (i & 127) << 2;
    if (rt < 4096) {
        split3_row(v + (size_t)rt * D_EMB + D_AUG, vs + (size_t)rt * 3 * D_AUG, D_AUG, c4, 0);
    } else if (rt < 4608) {
        int r = rt - 4096;
        split3_row(Wv + (size_t)r * D_AUG, wvs + (size_t)r * 3 * D_AUG, D_AUG, c4, 1);
    } else {
        int r = rt - 4608;
        split3_row(Wo + (size_t)r * D_EMB, wos + (size_t)r * 3 * D_AUG, D_AUG, c4, 1);
    }
}

// ---------------------------------------------------------------------------
// HMMA GEMM core (device fn): C[M,N] = A[M,K3] @ B[N,K3]^T
// ---------------------------------------------------------------------------
#define BM 128
#define BN 128
#define BK 32
#define LDSM 40
#define STAGES 3
#define TSTG (BM * LDSM)
#define GEMM_SMEM (2 * STAGES * TSTG * 2)

__device__ __forceinline__ void gemm_body(const __nv_bfloat16* __restrict__ A,
                                          const __nv_bfloat16* __restrict__ B,
                                          float* __restrict__ C, int K3, int ldc,
                                          int m0, int n0)
{
    __nv_bfloat16* As = (__nv_bfloat16*)dynsmem;
    __nv_bfloat16* Bs = As + STAGES * TSTG;

    const int tid  = threadIdx.x;
    const int wid  = tid >> 5, lane = tid & 31;
    const int wm   = (wid >> 2) * 64;
    const int wn   = (wid & 3) * 32;

    const int lrow0 = tid >> 2,         lq0 = tid & 3;
    const int lrow1 = (tid + 256) >> 2, lq1 = (tid + 256) & 3;

    const __nv_bfloat16* Ag0 = A + (size_t)(m0 + lrow0) * K3 + lq0 * 8;
    const __nv_bfloat16* Ag1 = A + (size_t)(m0 + lrow1) * K3 + lq1 * 8;
    const __nv_bfloat16* Bg0 = B + (size_t)(n0 + lrow0) * K3 + lq0 * 8;
    const __nv_bfloat16* Bg1 = B + (size_t)(n0 + lrow1) * K3 + lq1 * 8;
    const uint32_t sA0 = smem_u32(As) + (lrow0 * LDSM + lq0 * 8) * 2;
    const uint32_t sA1 = smem_u32(As) + (lrow1 * LDSM + lq1 * 8) * 2;
    const uint32_t sB0 = smem_u32(Bs) + (lrow0 * LDSM + lq0 * 8) * 2;
    const uint32_t sB1 = smem_u32(Bs) + (lrow1 * LDSM + lq1 * 8) * 2;

    const int KT = K3 / BK;

    float acc[4][4][4];
#pragma unroll
    for (int i = 0; i < 4; i++)
#pragma unroll
        for (int j = 0; j < 4; j++)
#pragma unroll
            for (int t = 0; t < 4; t++) acc[i][j][t] = 0.f;

    const uint32_t als = smem_u32(As) + ((wm + (lane & 15)) * LDSM + (lane >> 4) * 8) * 2;
    const uint32_t bls = smem_u32(Bs) + ((wn + (lane & 15)) * LDSM + (lane >> 4) * 8) * 2;

#pragma unroll
    for (int s = 0; s < STAGES - 1; s++) {
        int k0 = s * BK;
        cp16(sA0 + s * TSTG * 2, Ag0 + k0);
        cp16(sA1 + s * TSTG * 2, Ag1 + k0);
        cp16(sB0 + s * TSTG * 2, Bg0 + k0);
        cp16(sB1 + s * TSTG * 2, Bg1 + k0);
        cp_commit();
    }

    for (int it = 0; it < KT; it++) {
        cp_wait<STAGES - 2>();
        __syncthreads();
        const int sc = it % STAGES;
        const uint32_t abase = als + sc * TSTG * 2;
        const uint32_t bbase = bls + sc * TSTG * 2;
#pragma unroll
        for (int ks = 0; ks < 2; ks++) {
            uint32_t af[4][4], bf[2][4];
#pragma unroll
            for (int mt = 0; mt < 4; mt++)
                ldmx4(af[mt], abase + (mt * 16 * LDSM + ks * 16) * 2);
#pragma unroll
            for (int nt2 = 0; nt2 < 2; nt2++)
                ldmx4(bf[nt2], bbase + (nt2 * 16 * LDSM + ks * 16) * 2);
#pragma unroll
            for (int mt = 0; mt < 4; mt++)
#pragma unroll
                for (int nt = 0; nt < 4; nt++)
                    mma_bf16(acc[mt][nt], af[mt],
                             bf[nt >> 1][nt & 1], bf[nt >> 1][(nt & 1) + 2]);
        }
        const int nxt = it + STAGES - 1;
        if (nxt < KT) {
            const int sn = nxt % STAGES;
            const int k0 = nxt * BK;
            cp16(sA0 + sn * TSTG * 2, Ag0 + k0);
            cp16(sA1 + sn * TSTG * 2, Ag1 + k0);
            cp16(sB0 + sn * TSTG * 2, Bg0 + k0);
            cp16(sB1 + sn * TSTG * 2, Bg1 + k0);
        }
        cp_commit();
    }

    const int rbase = m0 + wm + (lane >> 2);
    const int cbase = n0 + wn + (lane & 3) * 2;
#pragma unroll
    for (int mt = 0; mt < 4; mt++) {
#pragma unroll
        for (int nt = 0; nt < 4; nt++) {
            float* p0 = C + (size_t)(rbase + mt * 16) * ldc + cbase + nt * 8;
            float* p1 = p0 + 8 * ldc;
            *(float2*)p0 = make_float2(acc[mt][nt][0], acc[mt][nt][1]);
            *(float2*)p1 = make_float2(acc[mt][nt][2], acc[mt][nt][3]);
        }
    }
}

// Generic single-GEMM launch (v-proj, o-proj)
__global__ void __launch_bounds__(256, 2)
gemm_hmma(const __nv_bfloat16* __restrict__ A, const __nv_bfloat16* __restrict__ B,
          float* __restrict__ C, int K3, int ldc)
{
    gemm_body(A, B, C, K3, ldc, blockIdx.y * BM, blockIdx.x * BN);
}

// Batched q+k projection: blockIdx.z selects operand set -> 256 CTAs, 2/SM.
__global__ void __launch_bounds__(256, 2)
gemm_qk2(const __nv_bfloat16* __restrict__ A0, const __nv_bfloat16* __restrict__ B0,
         float* __restrict__ C0,
         const __nv_bfloat16* __restrict__ A1, const __nv_bfloat16* __restrict__ B1,
         float* __restrict__ C1, int K3, int ldc)
{
    const __nv_bfloat16* A = blockIdx.z ? A1 : A0;
    const __nv_bfloat16* B = blockIdx.z ? B1 : B0;
    float* C = blockIdx.z ? C1 : C0;
    gemm_body(A, B, C, K3, ldc, blockIdx.y * BM, blockIdx.x * BN);
}

// ---------------------------------------------------------------------------
// RoPE table
// ---------------------------------------------------------------------------
__global__ void rope_table_kernel(float* __restrict__ tab)
{
    int idx = blockIdx.x * blockDim.x + threadIdx.x;   // 2048*64
    if (idx >= S_LEN * 64) return;
    int pair = idx & 63, s = idx >> 6;
    float freq = (float)exp(-(double)(2 * pair) * (1.0 / 128.0) * 9.210340371976184);
    float ang  = (float)s * freq;
    tab[idx]              = cosf(ang);
    tab[S_LEN * 64 + idx] = sinf(ang);
}

// ---------------------------------------------------------------------------
// RoPE + split-bf16 plane emission
// ---------------------------------------------------------------------------
__global__ void rope_split_kernel(const float* __restrict__ qh, const float* __restrict__ kh,
                                  const float* __restrict__ tab,
                                  __nv_bfloat16* __restrict__ qhi, __nv_bfloat16* __restrict__ qlo,
                                  __nv_bfloat16* __restrict__ khi, __nv_bfloat16* __restrict__ klo)
{
    int idx  = blockIdx.x * blockDim.x + threadIdx.x;  // 8*2048*64
    int pair = idx & 63;
    int s    = (idx >> 6) & (S_LEN - 1);
    int bh   = idx >> 17;
    int b = bh >> 2, h = bh & 3;

    float c  = tab[s * 64 + pair];
    float sn = tab[S_LEN * 64 + s * 64 + pair];

    size_t src = (size_t)(b * S_LEN + s) * D_AUG + h * 128 + 2 * pair;
    size_t dst = (size_t)bh * S_LEN * 128 + (size_t)s * 128 + 2 * pair;
    const float qscale = 0.08838834764831845f;

    float q1 = qh[src], q2 = qh[src + 1];
    float qa = (q1 * c - q2 * sn) * qscale;
    float qb = (q1 * sn + q2 * c) * qscale;
    __nv_bfloat16 ha = __float2bfloat16(qa), hb = __float2bfloat16(qb);
    __nv_bfloat162 hv; hv.x = ha; hv.y = hb;
    __nv_bfloat162 lv;
    lv.x = __float2bfloat16(qa - __bfloat162float(ha));
    lv.y = __float2bfloat16(qb - __bfloat162float(hb));
    *(__nv_bfloat162*)(qhi + dst) = hv;
    *(__nv_bfloat162*)(qlo + dst) = lv;

    float k1 = kh[src], k2 = kh[src + 1];
    float ka = k1 * c - k2 * sn;
    float kb = k1 * sn + k2 * c;
    ha = __float2bfloat16(ka); hb = __float2bfloat16(kb);
    hv.x = ha; hv.y = hb;
    lv.x = __float2bfloat16(ka - __bfloat162float(ha));
    lv.y = __float2bfloat16(kb - __bfloat162float(hb));
    *(__nv_bfloat162*)(khi + dst) = hv;
    *(__nv_bfloat162*)(klo + dst) = lv;
}

// ---------------------------------------------------------------------------
// V transpose + split
// ---------------------------------------------------------------------------
__global__ void vt_split_kernel(const float* __restrict__ vh,
                                __nv_bfloat16* __restrict__ vthi, __nv_bfloat16* __restrict__ vtlo)
{
    __shared__ float tile[32][33];
    int bh = blockIdx.z, b = bh >> 2, h = bh & 3;
    int tx = threadIdx.x, ty = threadIdx.y;
    int s_in = blockIdx.x * 32 + ty;
    int d_in = blockIdx.y * 32 + tx;
    tile[ty][tx] = vh[(size_t)(b * S_LEN + s_in) * D_AUG + h * 128 + d_in];
    __syncthreads();
    int d_out = blockIdx.y * 32 + ty;
    int s_out = blockIdx.x * 32 + tx;
    float v = tile[tx][ty];
    __nv_bfloat16 hi = __float2bfloat16(v);
    size_t dst = (size_t)bh * 128 * S_LEN + (size_t)d_out * S_LEN + s_out;
    vthi[dst] = hi;
    vtlo[dst] = __float2bfloat16(v - __bfloat162float(hi));
}

// ---------------------------------------------------------------------------
// HMMA flash attention
// ---------------------------------------------------------------------------
#define FB_QHI 0
#define FB_QLO 17408
#define FB_KHI 34816
#define FB_KLO 52224
#define FB_VHI 69632
#define FB_VLO 88064
#define FB_PHI 106496
#define FB_PLO 115712
#define FB_RED 124928
#define FB_SMEM 125952
#define L2E 1.4426950408889634f

__global__ void __launch_bounds__(256, 1)
flash_hmma(const __nv_bfloat16* __restrict__ qhi, const __nv_bfloat16* __restrict__ qlo,
           const __nv_bfloat16* __restrict__ khi, const __nv_bfloat16* __restrict__ klo,
           const __nv_bfloat16* __restrict__ vthi, const __nv_bfloat16* __restrict__ vtlo,
           __nv_bfloat16* __restrict__ attn_s)
{
    char* fsm = dynsmem;
    const uint32_t sb = smem_u32(fsm);
    float* red = (float*)(fsm + FB_RED);

    const int tid  = threadIdx.x;
    const int lane = tid & 31;
    const int wid  = tid >> 5;
    const int mw   = wid >> 1;
    const int nw   = wid & 1;
    const int bh   = blockIdx.y;
    const int b    = bh >> 2, hh = bh & 3;

    const size_t qkplane = (size_t)bh * S_LEN * 128;
    const size_t vplane  = (size_t)bh * 128 * S_LEN;

    const uint32_t aoffQ = (mw * 16 + (lane & 15)) * 272 + (lane >> 4) * 16;
    const uint32_t boffK = (nw * 32 + (lane & 15)) * 272 + (lane >> 4) * 16;
    const uint32_t aoffP = (mw * 16 + (lane & 15)) * 144 + (lane >> 4) * 16;
    const uint32_t boffV = (nw * 64 + (lane & 15)) * 144 + (lane >> 4) * 16;

    const int r0 = lane >> 2;
    const int c2 = (lane & 3) * 2;
    const int rloc0 = mw * 16 + r0;
    const int rloc1 = rloc0 + 8;

    for (int qq = 0; qq < 2; qq++) {
        const int qb = qq ? 31 - (int)blockIdx.x : (int)blockIdx.x;

        __syncthreads();
        {
            const __nv_bfloat16* srcs[2] = {qhi + qkplane + (size_t)qb * 64 * 128,
                                            qlo + qkplane + (size_t)qb * 64 * 128};
#pragma unroll
            for (int p = 0; p < 2; p++)
#pragma unroll
                for (int i = 0; i < 4; i++) {
                    int c = tid + i * 256;
                    int r = c >> 4, qx = c & 15;
                    cp16(sb + FB_QHI + p * 17408 + r * 272 + qx * 16,
                         srcs[p] + (size_t)r * 128 + qx * 8);
                }
            cp_commit();
        }
        cp_wait<0>();
        __syncthreads();

        float m0 = -1e30f, m1 = -1e30f, l0 = 0.f, l1 = 0.f;
        float o[8][4];
#pragma unroll
        for (int f = 0; f < 8; f++)
#pragma unroll
            for (int e = 0; e < 4; e++) o[f][e] = 0.f;

        for (int jb = 0; jb <= qb; jb++) {
            __syncthreads();
            {
                const __nv_bfloat16* ks[2] = {khi + qkplane + (size_t)jb * 64 * 128,
                                              klo + qkplane + (size_t)jb * 64 * 128};
#pragma unroll
                for (int p = 0; p < 2; p++)
#pragma unroll
                    for (int i = 0; i < 4; i++) {
                        int c = tid + i * 256;
                        int r = c >> 4, qx = c & 15;
                        cp16(sb + FB_KHI + p * 17408 + r * 272 + qx * 16,
                             ks[p] + (size_t)r * 128 + qx * 8);
                    }
                const __nv_bfloat16* vs[2] = {vthi + vplane + jb * 64,
                                              vtlo + vplane + jb * 64};
#pragma unroll
                for (int p = 0; p < 2; p++)
#pragma unroll
                    for (int i = 0; i < 4; i++) {
                        int c = tid + i * 256;
                        int r = c >> 3, qx = c & 7;
                        cp16(sb + FB_VHI + p * 18432 + r * 144 + qx * 16,
                             vs[p] + (size_t)r * S_LEN + qx * 8);
                    }
                cp_commit();
            }
            cp_wait<0>();
            __syncthreads();

            float sacc[4][4];
#pragma unroll
            for (int f = 0; f < 4; f++)
#pragma unroll
                for (int e = 0; e < 4; e++) sacc[f][e] = 0.f;

            const uint32_t aB[3] = {sb + FB_QHI, sb + FB_QHI, sb + FB_QLO};
            const uint32_t bB[3] = {sb + FB_KHI, sb + FB_KLO, sb + FB_KHI};
#pragma unroll
            for (int ps = 0; ps < 3; ps++) {
                const uint32_t ab = aB[ps] + aoffQ;
                const uint32_t bb0 = bB[ps] + boffK;
                const uint32_t bb1 = bb0 + 16 * 272;
#pragma unroll
                for (int ks = 0; ks < 8; ks++) {
                    uint32_t a[4], q0[4], q1[4];
                    ldmx4(a,  ab  + ks * 32);
                    ldmx4(q0, bb0 + ks * 32);
                    ldmx4(q1, bb1 + ks * 32);
                    mma_bf16(sacc[0], a, q0[0], q0[2]);
                    mma_bf16(sacc[1], a, q0[1], q0[3]);
                    mma_bf16(sacc[2], a, q1[0], q1[2]);
                    mma_bf16(sacc[3], a, q1[1], q1[3]);
                }
            }

            if (jb == qb) {
#pragma unroll
                for (int f = 0; f < 4; f++) {
                    int colb = nw * 32 + (f >> 1) * 16 + (f & 1) * 8 + c2;
#pragma unroll
                    for (int e = 0; e < 4; e++) {
                        int row = mw * 16 + r0 + ((e >> 1) << 3);
                        int col = colb + (e & 1);
                        if (col > row) sacc[f][e] = -1e30f;
                    }
                }
            }

            float pm0 = -1e30f, pm1 = -1e30f;
#pragma unroll
            for (int f = 0; f < 4; f++) {
                pm0 = fmaxf(pm0, fmaxf(sacc[f][0], sacc[f][1]));
                pm1 = fmaxf(pm1, fmaxf(sacc[f][2], sacc[f][3]));
            }
            pm0 = fmaxf(pm0, __shfl_xor_sync(0xffffffffu, pm0, 1));
            pm0 = fmaxf(pm0, __shfl_xor_sync(0xffffffffu, pm0, 2));
            pm1 = fmaxf(pm1, __shfl_xor_sync(0xffffffffu, pm1, 1));
            pm1 = fmaxf(pm1, __shfl_xor_sync(0xffffffffu, pm1, 2));
            if ((lane & 3) == 0) {
                red[nw * 64 + rloc0] = pm0;
                red[nw * 64 + rloc1] = pm1;
            }
            __syncthreads();
            float rm0 = fmaxf(red[rloc0], red[64 + rloc0]);
            float rm1 = fmaxf(red[rloc1], red[64 + rloc1]);
            float mn0 = fmaxf(m0, rm0), mn1 = fmaxf(m1, rm1);
            float scl0 = ex2((m0 - mn0) * L2E);
            float scl1 = ex2((m1 - mn1) * L2E);

            float ts0 = 0.f, ts1 = 0.f;
#pragma unroll
            for (int f = 0; f < 4; f++) {
                int col = nw * 32 + (f >> 1) * 16 + (f & 1) * 8 + c2;
                float p00 = ex2((sacc[f][0] - mn0) * L2E);
                float p01 = ex2((sacc[f][1] - mn0) * L2E);
                float p10 = ex2((sacc[f][2] - mn1) * L2E);
                float p11 = ex2((sacc[f][3] - mn1) * L2E);
                ts0 += p00 + p01;
                ts1 += p10 + p11;
                __nv_bfloat16 h00 = __float2bfloat16(p00), h01 = __float2bfloat16(p01);
                __nv_bfloat16 h10 = __float2bfloat16(p10), h11 = __float2bfloat16(p11);
                __nv_bfloat162 hv, lv;
                hv.x = h00; hv.y = h01;
                lv.x = __float2bfloat16(p00 - __bfloat162float(h00));
                lv.y = __float2bfloat16(p01 - __bfloat162float(h01));
                *(__nv_bfloat162*)(fsm + FB_PHI + rloc0 * 144 + col * 2) = hv;
                *(__nv_bfloat162*)(fsm + FB_PLO + rloc0 * 144 + col * 2) = lv;
                hv.x = h10; hv.y = h11;
                lv.x = __float2bfloat16(p10 - __bfloat162float(h10));
                lv.y = __float2bfloat16(p11 - __bfloat162float(h11));
                *(__nv_bfloat162*)(fsm + FB_PHI + rloc1 * 144 + col * 2) = hv;
                *(__nv_bfloat162*)(fsm + FB_PLO + rloc1 * 144 + col * 2) = lv;
            }
            ts0 += __shfl_xor_sync(0xffffffffu, ts0, 1);
            ts0 += __shfl_xor_sync(0xffffffffu, ts0, 2);
            ts1 += __shfl_xor_sync(0xffffffffu, ts1, 1);
            ts1 += __shfl_xor_sync(0xffffffffu, ts1, 2);
            if ((lane & 3) == 0) {
                red[128 + nw * 64 + rloc0] = ts0;
                red[128 + nw * 64 + rloc1] = ts1;
            }
            __syncthreads();
            l0 = l0 * scl0 + red[128 + rloc0] + red[128 + 64 + rloc0];
            l1 = l1 * scl1 + red[128 + rloc1] + red[128 + 64 + rloc1];
            m0 = mn0; m1 = mn1;
#pragma unroll
            for (int f = 0; f < 8; f++) {
                o[f][0] *= scl0; o[f][1] *= scl0;
                o[f][2] *= scl1; o[f][3] *= scl1;
            }

            const uint32_t aP[3] = {sb + FB_PHI, sb + FB_PHI, sb + FB_PLO};
            const uint32_t bV[3] = {sb + FB_VHI, sb + FB_VLO, sb + FB_VHI};
#pragma unroll
            for (int ps = 0; ps < 3; ps++) {
                const uint32_t ab = aP[ps] + aoffP;
                const uint32_t bb = bV[ps] + boffV;
#pragma unroll
                for (int ks = 0; ks < 4; ks++) {
                    uint32_t a[4];
                    ldmx4(a, ab + ks * 32);
#pragma unroll
                    for (int g2 = 0; g2 < 4; g2++) {
                        uint32_t qv[4];
                        ldmx4(qv, bb + g2 * (16 * 144) + ks * 32);
                        mma_bf16(o[g2 * 2 + 0], a, qv[0], qv[2]);
                        mma_bf16(o[g2 * 2 + 1], a, qv[1], qv[3]);
                    }
                }
            }
        }

        float inv0 = 1.0f / l0, inv1 = 1.0f / l1;
        size_t rg0 = (size_t)(b * S_LEN + qb * 64 + rloc0) * (3 * D_AUG);
        size_t rg1 = (size_t)(b * S_LEN + qb * 64 + rloc1) * (3 * D_AUG);
#pragma unroll
        for (int f = 0; f < 8; f++) {
            int col = hh * 128 + nw * 64 + (f >> 1) * 16 + (f & 1) * 8 + c2;
            float v0 = o[f][0] * inv0, v1 = o[f][1] * inv0;
            __nv_bfloat16 h0 = __float2bfloat16(v0), h1 = __float2bfloat16(v1);
            __nv_bfloat162 hv, lv;
            hv.x = h0; hv.y = h1;
            lv.x = __float2bfloat16(v0 - __bfloat162float(h0));
            lv.y = __float2bfloat16(v1 - __bfloat162float(h1));
            *(__nv_bfloat162*)(attn_s + rg0 + col)             = hv;
            *(__nv_bfloat162*)(attn_s + rg0 + col + D_AUG)     = hv;
            *(__nv_bfloat162*)(attn_s + rg0 + col + 2 * D_AUG) = lv;
            v0 = o[f][2] * inv1; v1 = o[f][3] * inv1;
            h0 = __float2bfloat16(v0); h1 = __float2bfloat16(v1);
            hv.x = h0; hv.y = h1;
            lv.x = __float2bfloat16(v0 - __bfloat162float(h0));
            lv.y = __float2bfloat16(v1 - __bfloat162float(h1));
            *(__nv_bfloat162*)(attn_s + rg1 + col)             = hv;
            *(__nv_bfloat162*)(attn_s + rg1 + col + D_AUG)     = hv;
            *(__nv_bfloat162*)(attn_s + rg1 + col + 2 * D_AUG) = lv;
        }
    }
}

// ---------------------------------------------------------------------------
extern "C" void kernel_launch(void* const* d_in, const int* in_sizes, int n_in,
                              void* d_out, int out_size)
{
    const float* q  = (const float*)d_in[0];
    const float* k  = (const float*)d_in[1];
    const float* v  = (const float*)d_in[2];
    const float* Wq = (const float*)d_in[3];
    const float* Wk = (const float*)d_in[4];
    const float* Wv = (const float*)d_in[5];
    const float* Wo = (const float*)d_in[6];
    float* out = (float*)d_out;

    float *qh, *kh, *vh, *rtab;
    cudaGetSymbolAddress((void**)&qh,   g_qh);
    cudaGetSymbolAddress((void**)&kh,   g_kh);
    cudaGetSymbolAddress((void**)&vh,   g_vh);
    cudaGetSymbolAddress((void**)&rtab, g_rope);
    __nv_bfloat16 *qs, *ks, *vs, *ats, *wqs, *wks, *wvs, *wos;
    __nv_bfloat16 *pqhi, *pqlo, *pkhi, *pklo, *pvthi, *pvtlo;
    cudaGetSymbolAddress((void**)&qs,  g_q_s);
    cudaGetSymbolAddress((void**)&ks,  g_k_s);
    cudaGetSymbolAddress((void**)&vs,  g_v_s);
    cudaGetSymbolAddress((void**)&ats, g_attn_s);
    cudaGetSymbolAddress((void**)&wqs, g_Wq_s);
    cudaGetSymbolAddress((void**)&wks, g_Wk_s);
    cudaGetSymbolAddress((void**)&wvs, g_Wv_s);
    cudaGetSymbolAddress((void**)&wos, g_Wo_s);
    cudaGetSymbolAddress((void**)&pqhi, g_qhi);
    cudaGetSymbolAddress((void**)&pqlo, g_qlo);
    cudaGetSymbolAddress((void**)&pkhi, g_khi);
    cudaGetSymbolAddress((void**)&pklo, g_klo);
    cudaGetSymbolAddress((void**)&pvthi, g_vthi);
    cudaGetSymbolAddress((void**)&pvtlo, g_vtlo);

    cudaFuncSetAttribute(gemm_hmma,  cudaFuncAttributeMaxDynamicSharedMemorySize, GEMM_SMEM);
    cudaFuncSetAttribute(gemm_qk2,   cudaFuncAttributeMaxDynamicSharedMemorySize, GEMM_SMEM);
    cudaFuncSetAttribute(flash_hmma, cudaFuncAttributeMaxDynamicSharedMemorySize, FB_SMEM);

    // #1 q+k split
    split_qk_kernel<<<12288, 256>>>(q, k, qs, ks);
    // #2 Wq+Wk split
    split_wqk_kernel<<<1536, 256>>>(Wq, Wk, wqs, wks);
    // #3 rope table
    rope_table_kernel<<<512, 256>>>(rtab);
    // #4 merged q+k projection (PROFILED launch): 256 CTAs -> 2/SM
    gemm_qk2<<<dim3(4, 32, 2), 256, GEMM_SMEM>>>(qs, wqs, qh, ks, wks, kh, 3 * D_EMB, D_AUG);
    // #5 v + Wv + Wo split
    split_vwo_kernel<<<3072, 256>>>(v, Wv, Wo, vs, wvs, wos);
    // #6 v projection
    gemm_hmma<<<dim3(4, 32), 256, GEMM_SMEM>>>(vs, wvs, vh, 3 * D_AUG, D_AUG);
    // #7 rope + plane split
    rope_split_kernel<<<4096, 256>>>(qh, kh, rtab, pqhi, pqlo, pkhi, pklo);
    // #8 V transpose + split
    vt_split_kernel<<<dim3(64, 4, 8), dim3(32, 32)>>>(vh, pvthi, pvtlo);
    // #9 flash attention
    flash_hmma<<<dim3(16, 8), 256, FB_SMEM>>>(pqhi, pqlo, pkhi, pklo, pvthi, pvtlo, ats);
    // #10 output projection
    gemm_hmma<<<dim3(12, 32), 256, GEMM_SMEM>>>(ats, wos, out, 3 * D_AUG, D_EMB);
}